// round 11
// baseline (speedup 1.0000x reference)
#include <cuda_runtime.h>
#include <cuda_bf16.h>
#include <math.h>

#define MB   256
#define TX   256
#define FDIM 128
#define NA   256
#define NS   512
#define VOC  1024
#define AH   10
#define TYD  10

// ---------------- scratch ----------------
__device__ float    g_gin[2][TX][MB][4 * NA];   // [m][u*4+g]  (gate-quad per unit)
__device__ float    g_a[TX][MB][NS];
__device__ unsigned g_abf[TX][MB][NS / 2];      // bf16x2-packed copy of g_a
__device__ float    g_hT[2][2][NA][MB];         // [dir][t&1][u][m] double-buffered
__device__ float    g_Ea[MB][TX][AH];
__device__ float    g_ctx[MB][NS];
__device__ float    g_sbuf[2][MB][NS];
__device__ float    g_cdec[MB][NS];
__device__ unsigned g_bar[16][32];              // [dir*8 + m-tile][pad 128B]

__device__ __forceinline__ float sigf(float x) { return 1.f / (1.f + expf(-x)); }
__device__ __forceinline__ float fsig(float x) { return __fdividef(1.f, 1.f + __expf(-x)); }
__device__ __forceinline__ float ftanh(float x) { return 1.f - __fdividef(2.f, __expf(2.f * x) + 1.f); }

#define FMA2(acc, a, b) asm("fma.rn.f32x2 %0, %1, %2, %0;" : "+l"(acc) : "l"(a), "l"(b))
#define PACK2(d, lo, hi) asm("mov.b64 %0, {%1, %2};" : "=l"(d) : "f"(lo), "f"(hi))
#define UNPACK2(lo, hi, v) asm("mov.b64 {%0, %1}, %2;" : "=f"(lo), "=f"(hi) : "l"(v))

__global__ void zero_bar_kernel()
{
    int i = blockIdx.x * 256 + threadIdx.x;
    if (i < 512) ((unsigned*)g_bar)[i] = 0u;
}

__global__ void init_dec_kernel()
{
    int i = blockIdx.x * 256 + threadIdx.x;
    if (i < MB * NS) {
        (&g_sbuf[0][0][0])[i] = 0.f;
        (&g_cdec[0][0])[i] = 0.f;
    }
}

// ---------------- encoder input projection (f32x2): Gin = X @ Wih^T + b ----------------
// output layout: g_gin[d][t][m][u*4+g]
__global__ void xproj_kernel(const float* __restrict__ X,
                             const float* __restrict__ Wf, const float* __restrict__ bf,
                             const float* __restrict__ Wb, const float* __restrict__ bb)
{
    int d = blockIdx.z;
    const float* W    = d ? Wb : Wf;
    const float* bias = d ? bb : bf;
    int col0 = blockIdx.x * 64;
    int row0 = blockIdx.y * 64;
    int t  = row0 >> 8;
    int m0 = row0 & 255;
    int xt = d ? (TX - 1 - t) : t;

    __shared__ float As[16][68];
    __shared__ float Bs[16][132];
    int tid = threadIdx.x;
    int ry = tid >> 4, rx = tid & 15;

    unsigned long long acc2[2][4];
    #pragma unroll
    for (int p = 0; p < 2; p++)
        #pragma unroll
        for (int j = 0; j < 4; j++) acc2[p][j] = 0ull;

    int lr = tid >> 2;
    int lk4 = (tid & 3) * 4;

    for (int k0 = 0; k0 < FDIM; k0 += 16) {
        float4 av = *(const float4*)(X + ((size_t)(m0 + lr) * TX + xt) * FDIM + k0 + lk4);
        As[lk4 + 0][lr] = av.x; As[lk4 + 1][lr] = av.y;
        As[lk4 + 2][lr] = av.z; As[lk4 + 3][lr] = av.w;
        float4 bv = *(const float4*)(W + (size_t)(col0 + lr) * FDIM + k0 + lk4);
        float vv[4] = {bv.x, bv.y, bv.z, bv.w};
        #pragma unroll
        for (int j = 0; j < 4; j++)
            *(float2*)&Bs[lk4 + j][lr * 2] = make_float2(vv[j], vv[j]);
        __syncthreads();
        #pragma unroll
        for (int kk = 0; kk < 16; kk++) {
            ulonglong2 ap = *(const ulonglong2*)&As[kk][ry * 4];
            ulonglong2 w0 = *(const ulonglong2*)&Bs[kk][rx * 8];
            ulonglong2 w1 = *(const ulonglong2*)&Bs[kk][rx * 8 + 4];
            FMA2(acc2[0][0], ap.x, w0.x); FMA2(acc2[0][1], ap.x, w0.y);
            FMA2(acc2[0][2], ap.x, w1.x); FMA2(acc2[0][3], ap.x, w1.y);
            FMA2(acc2[1][0], ap.y, w0.x); FMA2(acc2[1][1], ap.y, w0.y);
            FMA2(acc2[1][2], ap.y, w1.x); FMA2(acc2[1][3], ap.y, w1.y);
        }
        __syncthreads();
    }

    int c = col0 + rx * 4;
    float4 bv = *(const float4*)&bias[c];
    float rr[4][4];
    UNPACK2(rr[0][0], rr[1][0], acc2[0][0]); UNPACK2(rr[0][1], rr[1][1], acc2[0][1]);
    UNPACK2(rr[0][2], rr[1][2], acc2[0][2]); UNPACK2(rr[0][3], rr[1][3], acc2[0][3]);
    UNPACK2(rr[2][0], rr[3][0], acc2[1][0]); UNPACK2(rr[2][1], rr[3][1], acc2[1][1]);
    UNPACK2(rr[2][2], rr[3][2], acc2[1][2]); UNPACK2(rr[2][3], rr[3][3], acc2[1][3]);
    float bb4[4] = {bv.x, bv.y, bv.z, bv.w};
    #pragma unroll
    for (int r = 0; r < 4; r++) {
        int m = m0 + ry * 4 + r;
        float* gp = &g_gin[d][t][m][0];
        #pragma unroll
        for (int j = 0; j < 4; j++) {
            int cg = c + j;
            int u = cg & 255, g = cg >> 8;
            gp[u * 4 + g] = rr[r][j] + bb4[j];
        }
    }
}

// ---------------- persistent recurrence: both dirs fused per CTA ----------------
// grid (16 u-tiles, 8 m-tiles) = 128 CTAs, 128 threads, persistent (1/SM).
// CTA: 16 units (64 cols, [u*4+g] natural pairs) x 32 m, BOTH directions sequentially.
// Barrier wait for dir d is always covered by ~a full phase of the other dir's compute.
__global__ void __launch_bounds__(128, 1) lstm_all_kernel(const float* __restrict__ Whf,
                                                          const float* __restrict__ Whb)
{
    extern __shared__ float sm[];
    float* Wsm[2];
    Wsm[0] = sm;                     // Wf: [256][64]  64 KB
    Wsm[1] = sm + 256 * 64;          // Wb: [256][64]  64 KB
    float* AsD = sm + 2 * 256 * 64;  // [256][64] dup-pair h, 64 KB (shared per phase)
    float* Hs  = AsD + 256 * 64;     // [16][40] staging, 2.56 KB

    int u0 = blockIdx.x * 16;
    int m0 = blockIdx.y * 32;
    int tid = threadIdx.x;
    int mq = tid >> 4;               // 0..7 : 4 m rows each
    int cq = tid & 15;               // 0..15: unit ulocal = cq
    unsigned* barp[2] = { &g_bar[blockIdx.y][0], &g_bar[8 + blockIdx.y][0] };

    // ---- one-time W fill (natural col pairs: col = ulocal*4 + g) ----
    {
        int colt = tid & 63;         // 0..63
        int kh   = (tid >> 6) * 128; // two threads per col split k range
        int ulocal = colt >> 2, g = colt & 3;
        #pragma unroll 1
        for (int dd = 0; dd < 2; dd++) {
            const float* W = dd ? Whb : Whf;
            const float* src = &W[(size_t)(g * NA + u0 + ulocal) * NA + kh];
            float* dst = Wsm[dd];
            for (int k4 = 0; k4 < 32; k4++) {
                float4 v = *(const float4*)(src + k4 * 4);
                dst[(kh + k4 * 4 + 0) * 64 + colt] = v.x;
                dst[(kh + k4 * 4 + 1) * 64 + colt] = v.y;
                dst[(kh + k4 * 4 + 2) * 64 + colt] = v.z;
                dst[(kh + k4 * 4 + 3) * 64 + colt] = v.w;
            }
        }
    }

    float cst[2][4];
    #pragma unroll
    for (int dd = 0; dd < 2; dd++)
        #pragma unroll
        for (int mi = 0; mi < 4; mi++) cst[dd][mi] = 0.f;

    // gin registers: rgv[d][mi] = float4 {i,f,g,o} for (m, unit cq)
    float4 rgv[2][4];
    #pragma unroll
    for (int mi = 0; mi < 4; mi++)
        rgv[0][mi] = *(const float4*)&g_gin[0][0][m0 + mq * 4 + mi][(u0 + cq) * 4];

    for (int t = 0; t < TX; t++) {
        #pragma unroll 1
        for (int d = 0; d < 2; d++) {
            // ---- wait (bwd only; fwd wait is at the end of the iteration) ----
            if (d == 1 && t > 0) {
                if (tid == 0) {
                    unsigned tgt = 16u * (unsigned)t;
                    unsigned v;
                    do {
                        asm volatile("ld.acquire.gpu.global.u32 %0, [%1];"
                                     : "=r"(v) : "l"(barp[1]) : "memory");
                    } while (v < tgt);
                }
                __syncthreads();
            }

            // ---- AsD fill: h_d(t-1), duplicated pairs ----
            if (t == 0) {
                float4 z = make_float4(0.f, 0.f, 0.f, 0.f);
                for (int i = tid; i < 256 * 64 / 4; i += 128)
                    ((float4*)AsD)[i] = z;
            } else {
                const float* hsrc = &g_hT[d][(t - 1) & 1][0][0];
                for (int idx = tid; idx < 2048; idx += 128) {
                    int m4 = idx & 7;
                    int k  = idx >> 3;
                    float4 v = __ldcg((const float4*)&hsrc[(size_t)k * MB + m0 + m4 * 4]);
                    float* dst = &AsD[k * 64 + m4 * 8];
                    *(float4*)&dst[0] = make_float4(v.x, v.x, v.y, v.y);
                    *(float4*)&dst[4] = make_float4(v.z, v.z, v.w, v.w);
                }
            }
            __syncthreads();

            // ---- accumulators from gin: pairs {i,f},{g,o} per m ----
            unsigned long long acc2[4][2];
            #pragma unroll
            for (int mi = 0; mi < 4; mi++) {
                PACK2(acc2[mi][0], rgv[d][mi].x, rgv[d][mi].y);
                PACK2(acc2[mi][1], rgv[d][mi].z, rgv[d][mi].w);
            }

            // ---- K loop: per k, 3 LDS.128 + 8 FMA2 ----
            const float* Ws = Wsm[d];
            #pragma unroll 4
            for (int k = 0; k < NA; k++) {
                ulonglong2 aA = *(const ulonglong2*)&AsD[k * 64 + mq * 8];      // {m0,m0},{m1,m1}
                ulonglong2 aB = *(const ulonglong2*)&AsD[k * 64 + mq * 8 + 4];  // {m2,m2},{m3,m3}
                ulonglong2 wv = *(const ulonglong2*)&Ws[k * 64 + cq * 4];       // {Wi,Wf},{Wg,Wo}
                FMA2(acc2[0][0], aA.x, wv.x); FMA2(acc2[0][1], aA.x, wv.y);
                FMA2(acc2[1][0], aA.y, wv.x); FMA2(acc2[1][1], aA.y, wv.y);
                FMA2(acc2[2][0], aB.x, wv.x); FMA2(acc2[2][1], aB.x, wv.y);
                FMA2(acc2[3][0], aB.y, wv.x); FMA2(acc2[3][1], aB.y, wv.y);
            }

            // ---- gates + state; stage h into Hs[ulocal][m] ----
            #pragma unroll
            for (int mi = 0; mi < 4; mi++) {
                float iv, fv, gv, ov;
                UNPACK2(iv, fv, acc2[mi][0]);
                UNPACK2(gv, ov, acc2[mi][1]);
                float cn = fsig(fv) * cst[d][mi] + fsig(iv) * ftanh(gv);
                cst[d][mi] = cn;
                Hs[cq * 40 + mq * 4 + mi] = fsig(ov) * ftanh(cn);
            }
            __syncthreads();

            // ---- cooperative coalesced writes ----
            int tw = d ? (TX - 1 - t) : t;
            {
                float* hdst = &g_hT[d][t & 1][0][0];
                {   // hT[u][m]: 16u x 8 m-quads = 128 tasks
                    int uu = tid >> 3, m4 = tid & 7;
                    float4 v = *(float4*)&Hs[uu * 40 + m4 * 4];
                    *(float4*)&hdst[(size_t)(u0 + uu) * MB + m0 + m4 * 4] = v;
                }
                {   // g_a[m][u]: 32m x 4 u-quads = 128 tasks
                    int mm = tid >> 2, q = tid & 3;
                    float4 v = make_float4(Hs[(q * 4 + 0) * 40 + mm],
                                           Hs[(q * 4 + 1) * 40 + mm],
                                           Hs[(q * 4 + 2) * 40 + mm],
                                           Hs[(q * 4 + 3) * 40 + mm]);
                    *(float4*)&g_a[tw][m0 + mm][d * NA + u0 + q * 4] = v;
                }
                if (tid < 64) {  // bf16 pack: 32m x 2 chunks (8u each)
                    int mm = tid >> 1, ch = tid & 1;
                    unsigned w[4];
                    #pragma unroll
                    for (int j = 0; j < 4; j++) {
                        float f0 = Hs[(ch * 8 + 2 * j + 0) * 40 + mm];
                        float f1 = Hs[(ch * 8 + 2 * j + 1) * 40 + mm];
                        __nv_bfloat162 b = __float22bfloat162_rn(make_float2(f0, f1));
                        w[j] = *(unsigned*)&b;
                    }
                    *(uint4*)&g_abf[tw][m0 + mm][(d * NA + u0) / 2 + ch * 4] =
                        make_uint4(w[0], w[1], w[2], w[3]);
                }
            }

            __threadfence();
            __syncthreads();
            if (tid == 0)
                asm volatile("red.release.gpu.global.add.u32 [%0], %1;"
                             :: "l"(barp[d]), "r"(1u) : "memory");

            // ---- prefetch gin for the other dir's next phase ----
            {
                int nd = d ^ 1;
                int tt = (d == 0) ? t : t + 1;
                if (tt < TX) {
                    #pragma unroll
                    for (int mi = 0; mi < 4; mi++)
                        rgv[nd][mi] = *(const float4*)
                            &g_gin[nd][tt][m0 + mq * 4 + mi][(u0 + cq) * 4];
                }
            }
        }

        // ---- wait fwd-bar(t) (covered by the entire bwd phase) ----
        if (t + 1 < TX) {
            if (tid == 0) {
                unsigned tgt = 16u * (unsigned)(t + 1);
                unsigned v;
                do {
                    asm volatile("ld.acquire.gpu.global.u32 %0, [%1];"
                                 : "=r"(v) : "l"(barp[0]) : "memory");
                } while (v < tgt);
            }
            __syncthreads();
        }
    }
}

// ---------------- hoisted attention energies: Ea = a @ W1a^T ----------------
__global__ void ea_kernel(const float* __restrict__ W1)
{
    __shared__ float W1t[512][AH];
    int tid = threadIdx.x;
    for (int i = tid; i < 512 * AH; i += 256) {
        int h = i / 512, k = i - h * 512;
        W1t[k][h] = W1[h * 1024 + k];
    }
    __syncthreads();
    int r = blockIdx.x * 256 + tid;
    const float* arow = &g_a[0][0][0] + (size_t)r * NS;
    float e[AH] = {};
    for (int k = 0; k < 512; k += 4) {
        float4 av = *(const float4*)(arow + k);
        #pragma unroll
        for (int h = 0; h < AH; h++)
            e[h] += av.x * W1t[k][h] + av.y * W1t[k + 1][h]
                  + av.z * W1t[k + 2][h] + av.w * W1t[k + 3][h];
    }
    int tt = r >> 8;
    int m = r & 255;
    float* eo = &g_Ea[m][tt][0];
    #pragma unroll
    for (int h = 0; h < AH; h++) eo[h] = e[h];
}

// ---------------- attention ----------------
__global__ void attention_kernel(const float* __restrict__ W1, const float* __restrict__ b1,
                                 const float* __restrict__ W2, const float* __restrict__ b2,
                                 int pin)
{
    int m = blockIdx.x;
    int tid = threadIdx.x;
    int lane = tid & 31, warp = tid >> 5;
    __shared__ float Ss[NS];
    __shared__ float EsSh[AH];
    __shared__ float alpha[TX];
    __shared__ float red[8];
    __shared__ float sh_mx, sh_sum;

    const float* s_in = &g_sbuf[pin][m][0];
    Ss[tid] = s_in[tid];
    Ss[tid + 256] = s_in[tid + 256];
    __syncthreads();

    for (int h = warp; h < AH; h += 8) {
        float p = 0.f;
        for (int k = lane; k < NS; k += 32)
            p += Ss[k] * W1[h * 1024 + 512 + k];
        #pragma unroll
        for (int o = 16; o; o >>= 1) p += __shfl_xor_sync(0xffffffffu, p, o);
        if (lane == 0) EsSh[h] = p + b1[h];
    }
    __syncthreads();

    float sc = b2[0];
    {
        const float* ea = &g_Ea[m][tid][0];
        #pragma unroll
        for (int h = 0; h < AH; h++)
            sc += W2[h] * tanhf(ea[h] + EsSh[h]);
    }
    sc = fmaxf(sc, 0.f);

    float v = sc;
    #pragma unroll
    for (int o = 16; o; o >>= 1) v = fmaxf(v, __shfl_xor_sync(0xffffffffu, v, o));
    if (lane == 0) red[warp] = v;
    __syncthreads();
    if (tid == 0) {
        float mx = red[0];
        #pragma unroll
        for (int i = 1; i < 8; i++) mx = fmaxf(mx, red[i]);
        sh_mx = mx;
    }
    __syncthreads();
    float ev = expf(sc - sh_mx);
    float sv = ev;
    #pragma unroll
    for (int o = 16; o; o >>= 1) sv += __shfl_xor_sync(0xffffffffu, sv, o);
    if (lane == 0) red[warp] = sv;
    __syncthreads();
    if (tid == 0) {
        float s = 0.f;
        #pragma unroll
        for (int i = 0; i < 8; i++) s += red[i];
        sh_sum = s;
    }
    __syncthreads();
    alpha[tid] = ev / sh_sum;
    __syncthreads();

    const unsigned* ab = &g_abf[0][m][0] + tid;
    float ax = 0.f, ay = 0.f;
    #pragma unroll 8
    for (int t2 = 0; t2 < TX; t2++) {
        unsigned p = ab[(size_t)t2 * MB * (NS / 2)];
        __nv_bfloat162 b2v = *(__nv_bfloat162*)&p;
        float2 vv = __bfloat1622float2(b2v);
        float al = alpha[t2];
        ax += al * vv.x;
        ay += al * vv.y;
    }
    g_ctx[m][2 * tid + 0] = ax;
    g_ctx[m][2 * tid + 1] = ay;
}

// ---------------- decoder LSTM cell (f32x2) ----------------
__global__ void dec_cell_kernel(const float* __restrict__ Wih, const float* __restrict__ Whh,
                                const float* __restrict__ bc, int pin)
{
    int u0 = blockIdx.x * 16;
    int m0 = blockIdx.y * 64;
    int tid = threadIdx.x;
    int ul = tid & 15, mg = tid >> 4;
    int u = u0 + ul;

    __shared__ float As[32][68];
    __shared__ float Ws[32][132];

    unsigned long long acc2[2][4];
    #pragma unroll
    for (int g = 0; g < 4; g++) {
        float b = bc[g * NS + u];
        PACK2(acc2[0][g], b, b);
        acc2[1][g] = acc2[0][g];
    }

    for (int ph = 0; ph < 2; ph++) {
        const float* Arow = ph ? &g_sbuf[pin][0][0] : &g_ctx[0][0];
        const float* W = ph ? Whh : Wih;
        for (int k0 = 0; k0 < NS; k0 += 32) {
            #pragma unroll
            for (int i = 0; i < 2; i++) {
                int lin = tid + 256 * i;
                int mm = lin >> 3, kq = lin & 7;
                float4 f = *(const float4*)&Arow[(size_t)(m0 + mm) * NS + k0 + kq * 4];
                As[kq * 4 + 0][mm] = f.x; As[kq * 4 + 1][mm] = f.y;
                As[kq * 4 + 2][mm] = f.z; As[kq * 4 + 3][mm] = f.w;
            }
            #pragma unroll
            for (int i = 0; i < 2; i++) {
                int lin = tid + 256 * i;
                int r = lin >> 3, kq = lin & 7;
                int uu = r >> 2, g = r & 3;
                float4 f = *(const float4*)&W[(size_t)(g * NS + u0 + uu) * NS + k0 + kq * 4];
                float vv[4] = {f.x, f.y, f.z, f.w};
                #pragma unroll
                for (int j = 0; j < 4; j++)
                    *(float2*)&Ws[kq * 4 + j][r * 2] = make_float2(vv[j], vv[j]);
            }
            __syncthreads();
            #pragma unroll 8
            for (int kk = 0; kk < 32; kk++) {
                ulonglong2 ap = *(const ulonglong2*)&As[kk][mg * 4];
                ulonglong2 wA = *(const ulonglong2*)&Ws[kk][ul * 8];
                ulonglong2 wB = *(const ulonglong2*)&Ws[kk][ul * 8 + 4];
                FMA2(acc2[0][0], ap.x, wA.x); FMA2(acc2[0][1], ap.x, wA.y);
                FMA2(acc2[0][2], ap.x, wB.x); FMA2(acc2[0][3], ap.x, wB.y);
                FMA2(acc2[1][0], ap.y, wA.x); FMA2(acc2[1][1], ap.y, wA.y);
                FMA2(acc2[1][2], ap.y, wB.x); FMA2(acc2[1][3], ap.y, wB.y);
            }
            __syncthreads();
        }
    }

    #pragma unroll
    for (int p = 0; p < 2; p++) {
        float i0, i1, f0, f1, g0, g1, o0, o1;
        UNPACK2(i0, i1, acc2[p][0]);
        UNPACK2(f0, f1, acc2[p][1]);
        UNPACK2(g0, g1, acc2[p][2]);
        UNPACK2(o0, o1, acc2[p][3]);
        {
            int m = m0 + mg * 4 + 2 * p;
            float co = g_cdec[m][u];
            float cn = sigf(f0) * co + sigf(i0) * tanhf(g0);
            g_cdec[m][u] = cn;
            g_sbuf[1 - pin][m][u] = sigf(o0) * tanhf(cn);
        }
        {
            int m = m0 + mg * 4 + 2 * p + 1;
            float co = g_cdec[m][u];
            float cn = sigf(f1) * co + sigf(i1) * tanhf(g1);
            g_cdec[m][u] = cn;
            g_sbuf[1 - pin][m][u] = sigf(o1) * tanhf(cn);
        }
    }
}

// ---------------- output projection (f32x2) ----------------
__global__ void fc_kernel(const float* __restrict__ Wfc, const float* __restrict__ bfc,
                          float* __restrict__ outp, int ps, int ty)
{
    int col0 = blockIdx.x * 64;
    int m0 = blockIdx.y * 64;
    int tid = threadIdx.x;
    int ry = tid >> 4, rx = tid & 15;

    __shared__ float As[16][68];
    __shared__ float Bs[16][132];

    unsigned long long acc2[2][4];
    #pragma unroll
    for (int p = 0; p < 2; p++)
        #pragma unroll
        for (int j = 0; j < 4; j++) acc2[p][j] = 0ull;

    int lr = tid >> 2;
    int lk4 = (tid & 3) * 4;
    const float* S = &g_sbuf[ps][0][0];

    for (int k0 = 0; k0 < NS; k0 += 16) {
        float4 av = *(const float4*)(S + (size_t)(m0 + lr) * NS + k0 + lk4);
        As[lk4 + 0][lr] = av.x; As[lk4 + 1][lr] = av.y;
        As[lk4 + 2][lr] = av.z; As[lk4 + 3][lr] = av.w;
        float4 bv = *(const float4*)(Wfc + (size_t)(col0 + lr) * NS + k0 + lk4);
        float vv[4] = {bv.x, bv.y, bv.z, bv.w};
        #pragma unroll
        for (int j = 0; j < 4; j++)
            *(float2*)&Bs[lk4 + j][lr * 2] = make_float2(vv[j], vv[j]);
        __syncthreads();
        #pragma unroll
        for (int kk = 0; kk < 16; kk++) {
            ulonglong2 ap = *(const ulonglong2*)&As[kk][ry * 4];
            ulonglong2 w0 = *(const ulonglong2*)&Bs[kk][rx * 8];
            ulonglong2 w1 = *(const ulonglong2*)&Bs[kk][rx * 8 + 4];
            FMA2(acc2[0][0], ap.x, w0.x); FMA2(acc2[0][1], ap.x, w0.y);
            FMA2(acc2[0][2], ap.x, w1.x); FMA2(acc2[0][3], ap.x, w1.y);
            FMA2(acc2[1][0], ap.y, w0.x); FMA2(acc2[1][1], ap.y, w0.y);
            FMA2(acc2[1][2], ap.y, w1.x); FMA2(acc2[1][3], ap.y, w1.y);
        }
        __syncthreads();
    }

    int c = col0 + rx * 4;
    float4 bv = *(const float4*)&bfc[c];
    float r0[4], r1[4], r2[4], r3[4];
    UNPACK2(r0[0], r1[0], acc2[0][0]); UNPACK2(r0[1], r1[1], acc2[0][1]);
    UNPACK2(r0[2], r1[2], acc2[0][2]); UNPACK2(r0[3], r1[3], acc2[0][3]);
    UNPACK2(r2[0], r3[0], acc2[1][0]); UNPACK2(r2[1], r3[1], acc2[1][1]);
    UNPACK2(r2[2], r3[2], acc2[1][2]); UNPACK2(r2[3], r3[3], acc2[1][3]);
    int mA = m0 + ry * 4;
    float* o0 = &outp[((size_t)(mA + 0) * TYD + ty) * VOC + c];
    float* o1 = &outp[((size_t)(mA + 1) * TYD + ty) * VOC + c];
    float* o2 = &outp[((size_t)(mA + 2) * TYD + ty) * VOC + c];
    float* o3 = &outp[((size_t)(mA + 3) * TYD + ty) * VOC + c];
    *(float4*)o0 = make_float4(r0[0] + bv.x, r0[1] + bv.y, r0[2] + bv.z, r0[3] + bv.w);
    *(float4*)o1 = make_float4(r1[0] + bv.x, r1[1] + bv.y, r1[2] + bv.z, r1[3] + bv.w);
    *(float4*)o2 = make_float4(r2[0] + bv.x, r2[1] + bv.y, r2[2] + bv.z, r2[3] + bv.w);
    *(float4*)o3 = make_float4(r3[0] + bv.x, r3[1] + bv.y, r3[2] + bv.z, r3[3] + bv.w);
}

// ---------------- launch ----------------
extern "C" void kernel_launch(void* const* d_in, const int* in_sizes, int n_in,
                              void* d_out, int out_size)
{
    const float* X     = (const float*)d_in[0];
    const float* Wih_f = (const float*)d_in[1];
    const float* Whh_f = (const float*)d_in[2];
    const float* b_f   = (const float*)d_in[3];
    const float* Wih_b = (const float*)d_in[4];
    const float* Whh_b = (const float*)d_in[5];
    const float* b_b   = (const float*)d_in[6];
    const float* W1    = (const float*)d_in[7];
    const float* b1    = (const float*)d_in[8];
    const float* W2    = (const float*)d_in[9];
    const float* b2    = (const float*)d_in[10];
    const float* Wc_ih = (const float*)d_in[11];
    const float* Wc_hh = (const float*)d_in[12];
    const float* bc    = (const float*)d_in[13];
    const float* Wfc   = (const float*)d_in[14];
    const float* bfc   = (const float*)d_in[15];
    float* outp = (float*)d_out;

    const int LSTM_SMEM = (2 * 256 * 64 + 256 * 64 + 16 * 40) * 4;  // 199,168 B

    static int smem_set = 0;
    if (!smem_set) {
        cudaFuncSetAttribute(lstm_all_kernel,
                             cudaFuncAttributeMaxDynamicSharedMemorySize, LSTM_SMEM);
        smem_set = 1;
    }

    zero_bar_kernel<<<2, 256>>>();
    init_dec_kernel<<<512, 256>>>();
    xproj_kernel<<<dim3(16, 1024, 2), 256>>>(X, Wih_f, b_f, Wih_b, b_b);
    lstm_all_kernel<<<dim3(16, 8), 128, LSTM_SMEM>>>(Whh_f, Whh_b);
    ea_kernel<<<256, 256>>>(W1);

    int pin = 0;
    for (int ty = 0; ty < TYD; ty++) {
        attention_kernel<<<MB, 256>>>(W1, b1, W2, b2, pin);
        dec_cell_kernel<<<dim3(32, 4), 256>>>(Wc_ih, Wc_hh, bc, pin);
        fc_kernel<<<dim3(16, 4), 256>>>(Wfc, bfc, outp, 1 - pin, ty);
        pin = 1 - pin;
    }
}

// round 13
// speedup vs baseline: 1.1611x; 1.1611x over previous
#include <cuda_runtime.h>
#include <cuda_bf16.h>
#include <math.h>
#include <stdint.h>
#include <mma.h>

using namespace nvcuda;

#define MB   256
#define TX   256
#define FDIM 128
#define NA   256
#define NS   512
#define VOC  1024
#define AH   10
#define TYD  10

#define BLD 72     // B smem leading dim (bf16)
#define ALD 272    // A smem leading dim (bf16)
#define CLD 72     // C smem leading dim (float)

// ---------------- scratch ----------------
__device__ float    g_gin[2][TX][MB][4 * NA];   // [m][u*4+g]
__device__ float    g_a[TX][MB][NS];
__device__ unsigned g_abf[TX][MB][NS / 2];      // bf16x2-packed copy of g_a
__device__ unsigned g_hx[2][2][2][MB][NA / 2];  // [dir][buf][hi/lo][m][k2] bf16x2 planes
__device__ float    g_Ea[MB][TX][AH];
__device__ float    g_ctx[MB][NS];
__device__ float    g_sbuf[2][MB][NS];
__device__ float    g_cdec[MB][NS];
__device__ unsigned g_bar[8][32];               // [dir*4+mtile][pad 128B]

__device__ __forceinline__ float sigf(float x) { return 1.f / (1.f + expf(-x)); }
__device__ __forceinline__ float fsig(float x) { return __fdividef(1.f, 1.f + __expf(-x)); }
__device__ __forceinline__ float ftanh(float x) { return 1.f - __fdividef(2.f, __expf(2.f * x) + 1.f); }

#define FMA2(acc, a, b) asm("fma.rn.f32x2 %0, %1, %2, %0;" : "+l"(acc) : "l"(a), "l"(b))
#define PACK2(d, lo, hi) asm("mov.b64 %0, {%1, %2};" : "=l"(d) : "f"(lo), "f"(hi))
#define UNPACK2(lo, hi, v) asm("mov.b64 {%0, %1}, %2;" : "=f"(lo), "=f"(hi) : "l"(v))

__global__ void zero_bar_kernel()
{
    int i = threadIdx.x;
    if (i < 256) ((unsigned*)g_bar)[i] = 0u;
}

__global__ void init_dec_kernel()
{
    int i = blockIdx.x * 256 + threadIdx.x;
    if (i < MB * NS) {
        (&g_sbuf[0][0][0])[i] = 0.f;
        (&g_cdec[0][0])[i] = 0.f;
    }
}

// ---------------- encoder input projection (f32x2): Gin = X @ Wih^T + b ----------------
// output layout: g_gin[d][t][m][u*4+g]
__global__ void xproj_kernel(const float* __restrict__ X,
                             const float* __restrict__ Wf, const float* __restrict__ bf,
                             const float* __restrict__ Wb, const float* __restrict__ bb)
{
    int d = blockIdx.z;
    const float* W    = d ? Wb : Wf;
    const float* bias = d ? bb : bf;
    int col0 = blockIdx.x * 64;
    int row0 = blockIdx.y * 64;
    int t  = row0 >> 8;
    int m0 = row0 & 255;
    int xt = d ? (TX - 1 - t) : t;

    __shared__ float As[16][68];
    __shared__ float Bs[16][132];
    int tid = threadIdx.x;
    int ry = tid >> 4, rx = tid & 15;

    unsigned long long acc2[2][4];
    #pragma unroll
    for (int p = 0; p < 2; p++)
        #pragma unroll
        for (int j = 0; j < 4; j++) acc2[p][j] = 0ull;

    int lr = tid >> 2;
    int lk4 = (tid & 3) * 4;

    for (int k0 = 0; k0 < FDIM; k0 += 16) {
        float4 av = *(const float4*)(X + ((size_t)(m0 + lr) * TX + xt) * FDIM + k0 + lk4);
        As[lk4 + 0][lr] = av.x; As[lk4 + 1][lr] = av.y;
        As[lk4 + 2][lr] = av.z; As[lk4 + 3][lr] = av.w;
        float4 bv = *(const float4*)(W + (size_t)(col0 + lr) * FDIM + k0 + lk4);
        float vv[4] = {bv.x, bv.y, bv.z, bv.w};
        #pragma unroll
        for (int j = 0; j < 4; j++)
            *(float2*)&Bs[lk4 + j][lr * 2] = make_float2(vv[j], vv[j]);
        __syncthreads();
        #pragma unroll
        for (int kk = 0; kk < 16; kk++) {
            ulonglong2 ap = *(const ulonglong2*)&As[kk][ry * 4];
            ulonglong2 w0 = *(const ulonglong2*)&Bs[kk][rx * 8];
            ulonglong2 w1 = *(const ulonglong2*)&Bs[kk][rx * 8 + 4];
            FMA2(acc2[0][0], ap.x, w0.x); FMA2(acc2[0][1], ap.x, w0.y);
            FMA2(acc2[0][2], ap.x, w1.x); FMA2(acc2[0][3], ap.x, w1.y);
            FMA2(acc2[1][0], ap.y, w0.x); FMA2(acc2[1][1], ap.y, w0.y);
            FMA2(acc2[1][2], ap.y, w1.x); FMA2(acc2[1][3], ap.y, w1.y);
        }
        __syncthreads();
    }

    int c = col0 + rx * 4;
    float4 bv = *(const float4*)&bias[c];
    float rr[4][4];
    UNPACK2(rr[0][0], rr[1][0], acc2[0][0]); UNPACK2(rr[0][1], rr[1][1], acc2[0][1]);
    UNPACK2(rr[0][2], rr[1][2], acc2[0][2]); UNPACK2(rr[0][3], rr[1][3], acc2[0][3]);
    UNPACK2(rr[2][0], rr[3][0], acc2[1][0]); UNPACK2(rr[2][1], rr[3][1], acc2[1][1]);
    UNPACK2(rr[2][2], rr[3][2], acc2[1][2]); UNPACK2(rr[2][3], rr[3][3], acc2[1][3]);
    float bb4[4] = {bv.x, bv.y, bv.z, bv.w};
    #pragma unroll
    for (int r = 0; r < 4; r++) {
        int m = m0 + ry * 4 + r;
        float* gp = &g_gin[d][t][m][0];
        #pragma unroll
        for (int j = 0; j < 4; j++) {
            int cg = c + j;
            int u = cg & 255, g = cg >> 8;
            gp[u * 4 + g] = rr[r][j] + bb4[j];
        }
    }
}

// ---------------- persistent recurrence: wmma bf16-split (3-pass) ----------------
// grid (16 u-tiles, 4 m-tiles, 2 dirs) = 128 CTAs, 128 threads, persistent 1/SM.
// CTA: D[64 m x 64 cols] (cols = ulocal*4+g), K=256.
__global__ void __launch_bounds__(128, 1) lstm_all_kernel(const float* __restrict__ Whf,
                                                          const float* __restrict__ Whb)
{
    extern __shared__ char smc[];
    __nv_bfloat16* Bhi = (__nv_bfloat16*)smc;           // [256][BLD]
    __nv_bfloat16* Blo = Bhi + 256 * BLD;
    __nv_bfloat16* Ahi = Blo + 256 * BLD;               // [64][ALD]
    __nv_bfloat16* Alo = Ahi + 64 * ALD;
    float*         Cs  = (float*)(Alo + 64 * ALD);      // [64][CLD]

    int d = blockIdx.z;
    const float* W = d ? Whb : Whf;
    int u0 = blockIdx.x * 16;
    int m0 = blockIdx.y * 64;
    int tid = threadIdx.x;
    int wid = tid >> 5;
    unsigned* barp = &g_bar[d * 4 + blockIdx.y][0];

    // ---- one-time B fill: B[k][c] = split(W[(g*NA + u0+ul)*NA + k]), c = ul*4+g ----
    for (int idx = tid; idx < 256 * 64; idx += 128) {
        int k = idx >> 6, c = idx & 63;
        int ul = c >> 2, g = c & 3;
        float w = W[(size_t)(g * NA + u0 + ul) * NA + k];
        __nv_bfloat16 hi = __float2bfloat16(w);
        __nv_bfloat16 lo = __float2bfloat16(w - __bfloat162float(hi));
        Bhi[k * BLD + c] = hi;
        Blo[k * BLD + c] = lo;
    }

    int mloc = tid >> 1, half = tid & 1;
    int mabs = m0 + mloc;
    float cst[8];
    #pragma unroll
    for (int i = 0; i < 8; i++) cst[i] = 0.f;

    for (int t = 0; t < TX; t++) {
        // ---- wait + A-plane fill ----
        if (t > 0) {
            if (tid == 0) {
                unsigned tgt = 16u * (unsigned)t;
                unsigned v;
                do {
                    asm volatile("ld.acquire.gpu.global.u32 %0, [%1];"
                                 : "=r"(v) : "l"(barp) : "memory");
                } while (v < tgt);
            }
            __syncthreads();

            int buf = (t - 1) & 1;
            uint32_t* ah = (uint32_t*)Ahi;
            uint32_t* al = (uint32_t*)Alo;
            const unsigned* ph = &g_hx[d][buf][0][m0][0];
            const unsigned* pl = &g_hx[d][buf][1][m0][0];
            for (int idx = tid; idx < 64 * 128; idx += 128) {
                int m = idx >> 7, w2 = idx & 127;
                ah[m * (ALD / 2) + w2] = __ldcg(&ph[idx]);
                al[m * (ALD / 2) + w2] = __ldcg(&pl[idx]);
            }
        } else {
            for (int idx = tid; idx < 64 * (ALD / 2); idx += 128) {
                ((uint32_t*)Ahi)[idx] = 0u;
                ((uint32_t*)Alo)[idx] = 0u;
            }
        }
        __syncthreads();

        // ---- wmma 3-pass GEMM: warp wid owns m rows [wid*16, wid*16+16) ----
        wmma::fragment<wmma::accumulator, 16, 16, 16, float> acc[4];
        #pragma unroll
        for (int n = 0; n < 4; n++) wmma::fill_fragment(acc[n], 0.f);
        int wm = wid * 16;
        #pragma unroll 1
        for (int pass = 0; pass < 3; pass++) {
            const __nv_bfloat16* Ap = (pass == 2) ? Alo : Ahi;
            const __nv_bfloat16* Bp = (pass == 1) ? Blo : Bhi;
            #pragma unroll 1
            for (int k = 0; k < 16; k++) {
                wmma::fragment<wmma::matrix_a, 16, 16, 16, __nv_bfloat16, wmma::row_major> af;
                wmma::load_matrix_sync(af, Ap + wm * ALD + k * 16, ALD);
                #pragma unroll
                for (int n = 0; n < 4; n++) {
                    wmma::fragment<wmma::matrix_b, 16, 16, 16, __nv_bfloat16, wmma::row_major> bf;
                    wmma::load_matrix_sync(bf, Bp + (k * 16) * BLD + n * 16, BLD);
                    wmma::mma_sync(acc[n], af, bf, acc[n]);
                }
            }
        }
        #pragma unroll
        for (int n = 0; n < 4; n++)
            wmma::store_matrix_sync(Cs + wm * CLD + n * 16, acc[n], CLD, wmma::mem_row_major);
        __syncthreads();

        // ---- epilogue: thread = (mloc, half); units u0 + half*8 .. +7 ----
        int tw = d ? (TX - 1 - t) : t;
        int buf = t & 1;
        float gc[32];
        {
            const float4* gp = (const float4*)&g_gin[d][t][mabs][(u0 + half * 8) * 4];
            #pragma unroll
            for (int q = 0; q < 8; q++) *(float4*)&gc[q * 4] = gp[q];
        }
        float h8[8];
        #pragma unroll
        for (int j = 0; j < 8; j++) {
            int col = half * 32 + j * 4;
            float iv = Cs[mloc * CLD + col + 0] + gc[4 * j + 0];
            float fv = Cs[mloc * CLD + col + 1] + gc[4 * j + 1];
            float gv = Cs[mloc * CLD + col + 2] + gc[4 * j + 2];
            float ov = Cs[mloc * CLD + col + 3] + gc[4 * j + 3];
            float cn = fsig(fv) * cst[j] + fsig(iv) * ftanh(gv);
            cst[j] = cn;
            h8[j] = fsig(ov) * ftanh(cn);
        }
        // fp32 a
        {
            float* ga = &g_a[tw][mabs][d * NA + u0 + half * 8];
            *(float4*)&ga[0] = make_float4(h8[0], h8[1], h8[2], h8[3]);
            *(float4*)&ga[4] = make_float4(h8[4], h8[5], h8[6], h8[7]);
        }
        // bf16 hi/lo planes + abf
        {
            uint32_t phw[4], plw[4];
            #pragma unroll
            for (int j = 0; j < 4; j++) {
                float f0 = h8[2 * j], f1 = h8[2 * j + 1];
                __nv_bfloat162 bh = __float22bfloat162_rn(make_float2(f0, f1));
                float r0 = f0 - __bfloat162float(__low2bfloat16(bh));
                float r1 = f1 - __bfloat162float(__high2bfloat16(bh));
                __nv_bfloat162 bl = __float22bfloat162_rn(make_float2(r0, r1));
                phw[j] = *(uint32_t*)&bh;
                plw[j] = *(uint32_t*)&bl;
            }
            int woff = (u0 + half * 8) >> 1;
            uint4 vh = make_uint4(phw[0], phw[1], phw[2], phw[3]);
            uint4 vl = make_uint4(plw[0], plw[1], plw[2], plw[3]);
            __stcg((uint4*)&g_hx[d][buf][0][mabs][woff], vh);
            __stcg((uint4*)&g_hx[d][buf][1][mabs][woff], vl);
            *(uint4*)&g_abf[tw][mabs][(d * NA + u0) / 2 + half * 4] = vh;
        }

        __threadfence();
        __syncthreads();
        if (tid == 0)
            asm volatile("red.release.gpu.global.add.u32 [%0], %1;"
                         :: "l"(barp), "r"(1u) : "memory");
    }
}

// ---------------- hoisted attention energies: Ea = a @ W1a^T ----------------
__global__ void ea_kernel(const float* __restrict__ W1)
{
    __shared__ float W1t[512][AH];
    int tid = threadIdx.x;
    for (int i = tid; i < 512 * AH; i += 256) {
        int h = i / 512, k = i - h * 512;
        W1t[k][h] = W1[h * 1024 + k];
    }
    __syncthreads();
    int r = blockIdx.x * 256 + tid;
    const float* arow = &g_a[0][0][0] + (size_t)r * NS;
    float e[AH] = {};
    for (int k = 0; k < 512; k += 4) {
        float4 av = *(const float4*)(arow + k);
        #pragma unroll
        for (int h = 0; h < AH; h++)
            e[h] += av.x * W1t[k][h] + av.y * W1t[k + 1][h]
                  + av.z * W1t[k + 2][h] + av.w * W1t[k + 3][h];
    }
    int tt = r >> 8;
    int m = r & 255;
    float* eo = &g_Ea[m][tt][0];
    #pragma unroll
    for (int h = 0; h < AH; h++) eo[h] = e[h];
}

// ---------------- attention ----------------
__global__ void attention_kernel(const float* __restrict__ W1, const float* __restrict__ b1,
                                 const float* __restrict__ W2, const float* __restrict__ b2,
                                 int pin)
{
    int m = blockIdx.x;
    int tid = threadIdx.x;
    int lane = tid & 31, warp = tid >> 5;
    __shared__ float Ss[NS];
    __shared__ float EsSh[AH];
    __shared__ float alpha[TX];
    __shared__ float red[8];
    __shared__ float sh_mx, sh_sum;

    const float* s_in = &g_sbuf[pin][m][0];
    Ss[tid] = s_in[tid];
    Ss[tid + 256] = s_in[tid + 256];
    __syncthreads();

    for (int h = warp; h < AH; h += 8) {
        float p = 0.f;
        for (int k = lane; k < NS; k += 32)
            p += Ss[k] * W1[h * 1024 + 512 + k];
        #pragma unroll
        for (int o = 16; o; o >>= 1) p += __shfl_xor_sync(0xffffffffu, p, o);
        if (lane == 0) EsSh[h] = p + b1[h];
    }
    __syncthreads();

    float sc = b2[0];
    {
        const float* ea = &g_Ea[m][tid][0];
        #pragma unroll
        for (int h = 0; h < AH; h++)
            sc += W2[h] * tanhf(ea[h] + EsSh[h]);
    }
    sc = fmaxf(sc, 0.f);

    float v = sc;
    #pragma unroll
    for (int o = 16; o; o >>= 1) v = fmaxf(v, __shfl_xor_sync(0xffffffffu, v, o));
    if (lane == 0) red[warp] = v;
    __syncthreads();
    if (tid == 0) {
        float mx = red[0];
        #pragma unroll
        for (int i = 1; i < 8; i++) mx = fmaxf(mx, red[i]);
        sh_mx = mx;
    }
    __syncthreads();
    float ev = expf(sc - sh_mx);
    float sv = ev;
    #pragma unroll
    for (int o = 16; o; o >>= 1) sv += __shfl_xor_sync(0xffffffffu, sv, o);
    if (lane == 0) red[warp] = sv;
    __syncthreads();
    if (tid == 0) {
        float s = 0.f;
        #pragma unroll
        for (int i = 0; i < 8; i++) s += red[i];
        sh_sum = s;
    }
    __syncthreads();
    alpha[tid] = ev / sh_sum;
    __syncthreads();

    const unsigned* ab = &g_abf[0][m][0] + tid;
    float ax = 0.f, ay = 0.f;
    #pragma unroll 8
    for (int t2 = 0; t2 < TX; t2++) {
        unsigned p = ab[(size_t)t2 * MB * (NS / 2)];
        __nv_bfloat162 b2v = *(__nv_bfloat162*)&p;
        float2 vv = __bfloat1622float2(b2v);
        float al = alpha[t2];
        ax += al * vv.x;
        ay += al * vv.y;
    }
    g_ctx[m][2 * tid + 0] = ax;
    g_ctx[m][2 * tid + 1] = ay;
}

// ---------------- decoder LSTM cell (f32x2) ----------------
__global__ void dec_cell_kernel(const float* __restrict__ Wih, const float* __restrict__ Whh,
                                const float* __restrict__ bc, int pin)
{
    int u0 = blockIdx.x * 16;
    int m0 = blockIdx.y * 64;
    int tid = threadIdx.x;
    int ul = tid & 15, mg = tid >> 4;
    int u = u0 + ul;

    __shared__ float As[32][68];
    __shared__ float Ws[32][132];

    unsigned long long acc2[2][4];
    #pragma unroll
    for (int g = 0; g < 4; g++) {
        float b = bc[g * NS + u];
        PACK2(acc2[0][g], b, b);
        acc2[1][g] = acc2[0][g];
    }

    for (int ph = 0; ph < 2; ph++) {
        const float* Arow = ph ? &g_sbuf[pin][0][0] : &g_ctx[0][0];
        const float* W = ph ? Whh : Wih;
        for (int k0 = 0; k0 < NS; k0 += 32) {
            #pragma unroll
            for (int i = 0; i < 2; i++) {
                int lin = tid + 256 * i;
                int mm = lin >> 3, kq = lin & 7;
                float4 f = *(const float4*)&Arow[(size_t)(m0 + mm) * NS + k0 + kq * 4];
                As[kq * 4 + 0][mm] = f.x; As[kq * 4 + 1][mm] = f.y;
                As[kq * 4 + 2][mm] = f.z; As[kq * 4 + 3][mm] = f.w;
            }
            #pragma unroll
            for (int i = 0; i < 2; i++) {
                int lin = tid + 256 * i;
                int r = lin >> 3, kq = lin & 7;
                int uu = r >> 2, g = r & 3;
                float4 f = *(const float4*)&W[(size_t)(g * NS + u0 + uu) * NS + k0 + kq * 4];
                float vv[4] = {f.x, f.y, f.z, f.w};
                #pragma unroll
                for (int j = 0; j < 4; j++)
                    *(float2*)&Ws[kq * 4 + j][r * 2] = make_float2(vv[j], vv[j]);
            }
            __syncthreads();
            #pragma unroll 8
            for (int kk = 0; kk < 32; kk++) {
                ulonglong2 ap = *(const ulonglong2*)&As[kk][mg * 4];
                ulonglong2 wA = *(const ulonglong2*)&Ws[kk][ul * 8];
                ulonglong2 wB = *(const ulonglong2*)&Ws[kk][ul * 8 + 4];
                FMA2(acc2[0][0], ap.x, wA.x); FMA2(acc2[0][1], ap.x, wA.y);
                FMA2(acc2[0][2], ap.x, wB.x); FMA2(acc2[0][3], ap.x, wB.y);
                FMA2(acc2[1][0], ap.y, wA.x); FMA2(acc2[1][1], ap.y, wA.y);
                FMA2(acc2[1][2], ap.y, wB.x); FMA2(acc2[1][3], ap.y, wB.y);
            }
            __syncthreads();
        }
    }

    #pragma unroll
    for (int p = 0; p < 2; p++) {
        float i0, i1, f0, f1, g0, g1, o0, o1;
        UNPACK2(i0, i1, acc2[p][0]);
        UNPACK2(f0, f1, acc2[p][1]);
        UNPACK2(g0, g1, acc2[p][2]);
        UNPACK2(o0, o1, acc2[p][3]);
        {
            int m = m0 + mg * 4 + 2 * p;
            float co = g_cdec[m][u];
            float cn = sigf(f0) * co + sigf(i0) * tanhf(g0);
            g_cdec[m][u] = cn;
            g_sbuf[1 - pin][m][u] = sigf(o0) * tanhf(cn);
        }
        {
            int m = m0 + mg * 4 + 2 * p + 1;
            float co = g_cdec[m][u];
            float cn = sigf(f1) * co + sigf(i1) * tanhf(g1);
            g_cdec[m][u] = cn;
            g_sbuf[1 - pin][m][u] = sigf(o1) * tanhf(cn);
        }
    }
}

// ---------------- output projection (f32x2) ----------------
__global__ void fc_kernel(const float* __restrict__ Wfc, const float* __restrict__ bfc,
                          float* __restrict__ outp, int ps, int ty)
{
    int col0 = blockIdx.x * 64;
    int m0 = blockIdx.y * 64;
    int tid = threadIdx.x;
    int ry = tid >> 4, rx = tid & 15;

    __shared__ float As[16][68];
    __shared__ float Bs[16][132];

    unsigned long long acc2[2][4];
    #pragma unroll
    for (int p = 0; p < 2; p++)
        #pragma unroll
        for (int j = 0; j < 4; j++) acc2[p][j] = 0ull;

    int lr = tid >> 2;
    int lk4 = (tid & 3) * 4;
    const float* S = &g_sbuf[ps][0][0];

    for (int k0 = 0; k0 < NS; k0 += 16) {
        float4 av = *(const float4*)(S + (size_t)(m0 + lr) * NS + k0 + lk4);
        As[lk4 + 0][lr] = av.x; As[lk4 + 1][lr] = av.y;
        As[lk4 + 2][lr] = av.z; As[lk4 + 3][lr] = av.w;
        float4 bv = *(const float4*)(Wfc + (size_t)(col0 + lr) * NS + k0 + lk4);
        float vv[4] = {bv.x, bv.y, bv.z, bv.w};
        #pragma unroll
        for (int j = 0; j < 4; j++)
            *(float2*)&Bs[lk4 + j][lr * 2] = make_float2(vv[j], vv[j]);
        __syncthreads();
        #pragma unroll
        for (int kk = 0; kk < 16; kk++) {
            ulonglong2 ap = *(const ulonglong2*)&As[kk][ry * 4];
            ulonglong2 w0 = *(const ulonglong2*)&Bs[kk][rx * 8];
            ulonglong2 w1 = *(const ulonglong2*)&Bs[kk][rx * 8 + 4];
            FMA2(acc2[0][0], ap.x, w0.x); FMA2(acc2[0][1], ap.x, w0.y);
            FMA2(acc2[0][2], ap.x, w1.x); FMA2(acc2[0][3], ap.x, w1.y);
            FMA2(acc2[1][0], ap.y, w0.x); FMA2(acc2[1][1], ap.y, w0.y);
            FMA2(acc2[1][2], ap.y, w1.x); FMA2(acc2[1][3], ap.y, w1.y);
        }
        __syncthreads();
    }

    int c = col0 + rx * 4;
    float4 bv = *(const float4*)&bfc[c];
    float r0[4], r1[4], r2[4], r3[4];
    UNPACK2(r0[0], r1[0], acc2[0][0]); UNPACK2(r0[1], r1[1], acc2[0][1]);
    UNPACK2(r0[2], r1[2], acc2[0][2]); UNPACK2(r0[3], r1[3], acc2[0][3]);
    UNPACK2(r2[0], r3[0], acc2[1][0]); UNPACK2(r2[1], r3[1], acc2[1][1]);
    UNPACK2(r2[2], r3[2], acc2[1][2]); UNPACK2(r2[3], r3[3], acc2[1][3]);
    int mA = m0 + ry * 4;
    float* o0 = &outp[((size_t)(mA + 0) * TYD + ty) * VOC + c];
    float* o1 = &outp[((size_t)(mA + 1) * TYD + ty) * VOC + c];
    float* o2 = &outp[((size_t)(mA + 2) * TYD + ty) * VOC + c];
    float* o3 = &outp[((size_t)(mA + 3) * TYD + ty) * VOC + c];
    *(float4*)o0 = make_float4(r0[0] + bv.x, r0[1] + bv.y, r0[2] + bv.z, r0[3] + bv.w);
    *(float4*)o1 = make_float4(r1[0] + bv.x, r1[1] + bv.y, r1[2] + bv.z, r1[3] + bv.w);
    *(float4*)o2 = make_float4(r2[0] + bv.x, r2[1] + bv.y, r2[2] + bv.z, r2[3] + bv.w);
    *(float4*)o3 = make_float4(r3[0] + bv.x, r3[1] + bv.y, r3[2] + bv.z, r3[3] + bv.w);
}

// ---------------- launch ----------------
extern "C" void kernel_launch(void* const* d_in, const int* in_sizes, int n_in,
                              void* d_out, int out_size)
{
    const float* X     = (const float*)d_in[0];
    const float* Wih_f = (const float*)d_in[1];
    const float* Whh_f = (const float*)d_in[2];
    const float* b_f   = (const float*)d_in[3];
    const float* Wih_b = (const float*)d_in[4];
    const float* Whh_b = (const float*)d_in[5];
    const float* b_b   = (const float*)d_in[6];
    const float* W1    = (const float*)d_in[7];
    const float* b1    = (const float*)d_in[8];
    const float* W2    = (const float*)d_in[9];
    const float* b2    = (const float*)d_in[10];
    const float* Wc_ih = (const float*)d_in[11];
    const float* Wc_hh = (const float*)d_in[12];
    const float* bc    = (const float*)d_in[13];
    const float* Wfc   = (const float*)d_in[14];
    const float* bfc   = (const float*)d_in[15];
    float* outp = (float*)d_out;

    const int LSTM_SMEM = (2 * 256 * BLD + 2 * 64 * ALD) * 2 + 64 * CLD * 4;  // 161,792 B

    static int smem_set = 0;
    if (!smem_set) {
        cudaFuncSetAttribute(lstm_all_kernel,
                             cudaFuncAttributeMaxDynamicSharedMemorySize, LSTM_SMEM);
        smem_set = 1;
    }

    zero_bar_kernel<<<1, 256>>>();
    init_dec_kernel<<<512, 256>>>();
    xproj_kernel<<<dim3(16, 1024, 2), 256>>>(X, Wih_f, b_f, Wih_b, b_b);
    lstm_all_kernel<<<dim3(16, 4, 2), 128, LSTM_SMEM>>>(Whh_f, Whh_b);
    ea_kernel<<<256, 256>>>(W1);

    int pin = 0;
    for (int ty = 0; ty < TYD; ty++) {
        attention_kernel<<<MB, 256>>>(W1, b1, W2, b2, pin);
        dec_cell_kernel<<<dim3(32, 4), 256>>>(Wc_ih, Wc_hh, bc, pin);
        fc_kernel<<<dim3(16, 4), 256>>>(Wfc, bfc, outp, 1 - pin, ty);
        pin = 1 - pin;
    }
}

// round 14
// speedup vs baseline: 1.3887x; 1.1960x over previous
#include <cuda_runtime.h>
#include <cuda_bf16.h>
#include <math.h>
#include <stdint.h>
#include <mma.h>

using namespace nvcuda;

#define MB   256
#define TX   256
#define FDIM 128
#define NA   256
#define NS   512
#define VOC  1024
#define AH   10
#define TYD  10

#define BLD 72     // lstm B smem leading dim (bf16)
#define ALD 272    // lstm A smem leading dim (bf16)
#define CLD 72     // lstm C smem leading dim (float)

#define XBLD 72    // xproj B smem leading dim (bf16)
#define XALD 136   // xproj A smem leading dim (bf16)
#define XCLD 72    // xproj C smem leading dim (float)

// ---------------- scratch ----------------
__device__ float    g_gin[2][TX][MB][4 * NA];   // [m][u*4+g]
__device__ float    g_a[TX][MB][NS];
__device__ unsigned g_abf[TX][MB][NS / 2];      // bf16x2-packed copy of g_a
__device__ unsigned g_hx[2][2][2][MB][NA / 2];  // [dir][buf][hi/lo][m][k2] bf16x2 planes
__device__ float    g_Ea[MB][TX][AH];
__device__ float    g_ctx[MB][NS];
__device__ float    g_sbuf[2][MB][NS];
__device__ float    g_cdec[MB][NS];
__device__ unsigned g_bar[8][32];               // [dir*4+mtile][pad 128B]

__device__ __forceinline__ float sigf(float x) { return 1.f / (1.f + expf(-x)); }
__device__ __forceinline__ float fsig(float x) { return __fdividef(1.f, 1.f + __expf(-x)); }
__device__ __forceinline__ float ftanh(float x) { return 1.f - __fdividef(2.f, __expf(2.f * x) + 1.f); }

#define FMA2(acc, a, b) asm("fma.rn.f32x2 %0, %1, %2, %0;" : "+l"(acc) : "l"(a), "l"(b))
#define PACK2(d, lo, hi) asm("mov.b64 %0, {%1, %2};" : "=l"(d) : "f"(lo), "f"(hi))
#define UNPACK2(lo, hi, v) asm("mov.b64 {%0, %1}, %2;" : "=f"(lo), "=f"(hi) : "l"(v))

__global__ void zero_bar_kernel()
{
    int i = threadIdx.x;
    if (i < 256) ((unsigned*)g_bar)[i] = 0u;
}

__global__ void init_dec_kernel()
{
    int i = blockIdx.x * 256 + threadIdx.x;
    if (i < MB * NS) {
        (&g_sbuf[0][0][0])[i] = 0.f;
        (&g_cdec[0][0])[i] = 0.f;
    }
}

// ---------------- encoder input projection: wmma bf16-split (3-pass) ----------------
// Gin[t*256+m][c] = X[m, xt, :] @ W[c, :]^T + bias[c];  output layout g_gin[d][t][m][u*4+g].
// grid (16 c-tiles, 1024 r-tiles, 2 dirs), 128 threads, 2 CTAs/SM (90KB smem).
__global__ void __launch_bounds__(128) xproj_kernel(const float* __restrict__ X,
                             const float* __restrict__ Wf, const float* __restrict__ bf,
                             const float* __restrict__ Wb, const float* __restrict__ bb)
{
    extern __shared__ char xsm[];
    __nv_bfloat16* Bhi = (__nv_bfloat16*)xsm;          // [128][XBLD]
    __nv_bfloat16* Blo = Bhi + 128 * XBLD;
    __nv_bfloat16* Ahi = Blo + 128 * XBLD;             // [64][XALD]
    __nv_bfloat16* Alo = Ahi + 64 * XALD;
    float*         Cs  = (float*)(Alo + 64 * XALD);    // [64][XCLD]

    int d = blockIdx.z;
    const float* W    = d ? Wb : Wf;
    const float* bias = d ? bb : bf;
    int col0 = blockIdx.x * 64;
    int row0 = blockIdx.y * 64;
    int t  = row0 >> 8;
    int m0 = row0 & 255;
    int xt = d ? (TX - 1 - t) : t;

    int tid = threadIdx.x;
    int wid = tid >> 5;
    int lr = tid >> 1, kh = tid & 1;

    // ---- A fill: X rows, split hi/lo ----
    {
        const float* xrow = X + ((size_t)(m0 + lr) * TX + xt) * FDIM + kh * 64;
        #pragma unroll
        for (int j = 0; j < 16; j++) {
            float4 v = *(const float4*)(xrow + j * 4);
            float vv[4] = {v.x, v.y, v.z, v.w};
            #pragma unroll
            for (int e = 0; e < 4; e++) {
                __nv_bfloat16 hi = __float2bfloat16(vv[e]);
                __nv_bfloat16 lo = __float2bfloat16(vv[e] - __bfloat162float(hi));
                Ahi[lr * XALD + kh * 64 + j * 4 + e] = hi;
                Alo[lr * XALD + kh * 64 + j * 4 + e] = lo;
            }
        }
    }
    // ---- B fill: W rows transposed -> Bs[k][c], split hi/lo ----
    {
        int c = col0 + lr;
        const float* wrow = W + (size_t)c * FDIM + kh * 64;
        #pragma unroll
        for (int j = 0; j < 16; j++) {
            float4 v = *(const float4*)(wrow + j * 4);
            float vv[4] = {v.x, v.y, v.z, v.w};
            #pragma unroll
            for (int e = 0; e < 4; e++) {
                int k = kh * 64 + j * 4 + e;
                __nv_bfloat16 hi = __float2bfloat16(vv[e]);
                __nv_bfloat16 lo = __float2bfloat16(vv[e] - __bfloat162float(hi));
                Bhi[k * XBLD + lr] = hi;
                Blo[k * XBLD + lr] = lo;
            }
        }
    }
    __syncthreads();

    // ---- 3-pass wmma: warp wid owns m rows [wid*16, +16) ----
    wmma::fragment<wmma::accumulator, 16, 16, 16, float> acc[4];
    #pragma unroll
    for (int n = 0; n < 4; n++) wmma::fill_fragment(acc[n], 0.f);
    int wm = wid * 16;
    #pragma unroll 1
    for (int pass = 0; pass < 3; pass++) {
        const __nv_bfloat16* Ap = (pass == 2) ? Alo : Ahi;
        const __nv_bfloat16* Bp = (pass == 1) ? Blo : Bhi;
        #pragma unroll 1
        for (int kf = 0; kf < 8; kf++) {
            wmma::fragment<wmma::matrix_a, 16, 16, 16, __nv_bfloat16, wmma::row_major> af;
            wmma::load_matrix_sync(af, Ap + wm * XALD + kf * 16, XALD);
            #pragma unroll
            for (int n = 0; n < 4; n++) {
                wmma::fragment<wmma::matrix_b, 16, 16, 16, __nv_bfloat16, wmma::row_major> bfr;
                wmma::load_matrix_sync(bfr, Bp + (kf * 16) * XBLD + n * 16, XBLD);
                wmma::mma_sync(acc[n], af, bfr, acc[n]);
            }
        }
    }
    #pragma unroll
    for (int n = 0; n < 4; n++)
        wmma::store_matrix_sync(Cs + wm * XCLD + n * 16, acc[n], XCLD, wmma::mem_row_major);
    __syncthreads();

    // ---- epilogue: +bias, scatter to [u*4+g] layout ----
    {
        int mloc = tid >> 1, half = tid & 1;
        int m = m0 + mloc;
        float* gp = &g_gin[d][t][m][0];
        int g = col0 >> 8;
        #pragma unroll
        for (int j = 0; j < 32; j++) {
            int cg = col0 + half * 32 + j;
            int u = cg & 255;
            gp[u * 4 + g] = Cs[mloc * XCLD + half * 32 + j] + __ldg(&bias[cg]);
        }
    }
}

// ---------------- persistent recurrence: wmma bf16-split (3-pass) ----------------
// grid (16 u-tiles, 4 m-tiles, 2 dirs) = 128 CTAs, 128 threads, persistent 1/SM.
// CTA: D[64 m x 64 cols] (cols = ulocal*4+g), K=256.
__global__ void __launch_bounds__(128, 1) lstm_all_kernel(const float* __restrict__ Whf,
                                                          const float* __restrict__ Whb)
{
    extern __shared__ char smc[];
    __nv_bfloat16* Bhi = (__nv_bfloat16*)smc;           // [256][BLD]
    __nv_bfloat16* Blo = Bhi + 256 * BLD;
    __nv_bfloat16* Ahi = Blo + 256 * BLD;               // [64][ALD]
    __nv_bfloat16* Alo = Ahi + 64 * ALD;
    float*         Cs  = (float*)(Alo + 64 * ALD);      // [64][CLD]

    int d = blockIdx.z;
    const float* W = d ? Whb : Whf;
    int u0 = blockIdx.x * 16;
    int m0 = blockIdx.y * 64;
    int tid = threadIdx.x;
    int wid = tid >> 5;
    unsigned* barp = &g_bar[d * 4 + blockIdx.y][0];

    // ---- one-time B fill: B[k][c] = split(W[(g*NA + u0+ul)*NA + k]), c = ul*4+g ----
    for (int idx = tid; idx < 256 * 64; idx += 128) {
        int k = idx >> 6, c = idx & 63;
        int ul = c >> 2, g = c & 3;
        float w = W[(size_t)(g * NA + u0 + ul) * NA + k];
        __nv_bfloat16 hi = __float2bfloat16(w);
        __nv_bfloat16 lo = __float2bfloat16(w - __bfloat162float(hi));
        Bhi[k * BLD + c] = hi;
        Blo[k * BLD + c] = lo;
    }

    int mloc = tid >> 1, half = tid & 1;
    int mabs = m0 + mloc;
    float cst[8];
    #pragma unroll
    for (int i = 0; i < 8; i++) cst[i] = 0.f;

    for (int t = 0; t < TX; t++) {
        // ---- wait + A-plane fill (uint4) ----
        if (t > 0) {
            if (tid == 0) {
                unsigned tgt = 16u * (unsigned)t;
                unsigned v;
                do {
                    asm volatile("ld.acquire.gpu.global.u32 %0, [%1];"
                                 : "=r"(v) : "l"(barp) : "memory");
                } while (v < tgt);
            }
            __syncthreads();

            int buf = (t - 1) & 1;
            uint4* ah4 = (uint4*)Ahi;
            uint4* al4 = (uint4*)Alo;
            const uint4* ph = (const uint4*)&g_hx[d][buf][0][m0][0];
            const uint4* pl = (const uint4*)&g_hx[d][buf][1][m0][0];
            for (int idx = tid; idx < 64 * 32; idx += 128) {
                int m = idx >> 5, w4 = idx & 31;
                ah4[m * (ALD / 8) + w4] = __ldcg(&ph[idx]);
                al4[m * (ALD / 8) + w4] = __ldcg(&pl[idx]);
            }
        } else {
            uint4 z4 = make_uint4(0u, 0u, 0u, 0u);
            for (int idx = tid; idx < 64 * (ALD / 8); idx += 128) {
                ((uint4*)Ahi)[idx] = z4;
                ((uint4*)Alo)[idx] = z4;
            }
        }
        __syncthreads();

        // ---- wmma 3-pass GEMM: warp wid owns m rows [wid*16, wid*16+16) ----
        wmma::fragment<wmma::accumulator, 16, 16, 16, float> acc[4];
        #pragma unroll
        for (int n = 0; n < 4; n++) wmma::fill_fragment(acc[n], 0.f);
        int wm = wid * 16;
        #pragma unroll 1
        for (int pass = 0; pass < 3; pass++) {
            const __nv_bfloat16* Ap = (pass == 2) ? Alo : Ahi;
            const __nv_bfloat16* Bp = (pass == 1) ? Blo : Bhi;
            #pragma unroll 1
            for (int k = 0; k < 16; k++) {
                wmma::fragment<wmma::matrix_a, 16, 16, 16, __nv_bfloat16, wmma::row_major> af;
                wmma::load_matrix_sync(af, Ap + wm * ALD + k * 16, ALD);
                #pragma unroll
                for (int n = 0; n < 4; n++) {
                    wmma::fragment<wmma::matrix_b, 16, 16, 16, __nv_bfloat16, wmma::row_major> bfr;
                    wmma::load_matrix_sync(bfr, Bp + (k * 16) * BLD + n * 16, BLD);
                    wmma::mma_sync(acc[n], af, bfr, acc[n]);
                }
            }
        }
        #pragma unroll
        for (int n = 0; n < 4; n++)
            wmma::store_matrix_sync(Cs + wm * CLD + n * 16, acc[n], CLD, wmma::mem_row_major);
        __syncthreads();

        // ---- epilogue: thread = (mloc, half); units u0 + half*8 .. +7 ----
        int tw = d ? (TX - 1 - t) : t;
        int buf = t & 1;
        float gc[32];
        {
            const float4* gp = (const float4*)&g_gin[d][t][mabs][(u0 + half * 8) * 4];
            #pragma unroll
            for (int q = 0; q < 8; q++) *(float4*)&gc[q * 4] = gp[q];
        }
        float h8[8];
        #pragma unroll
        for (int j = 0; j < 8; j++) {
            int col = half * 32 + j * 4;
            float iv = Cs[mloc * CLD + col + 0] + gc[4 * j + 0];
            float fv = Cs[mloc * CLD + col + 1] + gc[4 * j + 1];
            float gv = Cs[mloc * CLD + col + 2] + gc[4 * j + 2];
            float ov = Cs[mloc * CLD + col + 3] + gc[4 * j + 3];
            float cn = fsig(fv) * cst[j] + fsig(iv) * ftanh(gv);
            cst[j] = cn;
            h8[j] = fsig(ov) * ftanh(cn);
        }
        // fp32 a
        {
            float* ga = &g_a[tw][mabs][d * NA + u0 + half * 8];
            *(float4*)&ga[0] = make_float4(h8[0], h8[1], h8[2], h8[3]);
            *(float4*)&ga[4] = make_float4(h8[4], h8[5], h8[6], h8[7]);
        }
        // bf16 hi/lo planes + abf
        {
            uint32_t phw[4], plw[4];
            #pragma unroll
            for (int j = 0; j < 4; j++) {
                float f0 = h8[2 * j], f1 = h8[2 * j + 1];
                __nv_bfloat162 bh = __float22bfloat162_rn(make_float2(f0, f1));
                float r0 = f0 - __bfloat162float(__low2bfloat16(bh));
                float r1 = f1 - __bfloat162float(__high2bfloat16(bh));
                __nv_bfloat162 bl = __float22bfloat162_rn(make_float2(r0, r1));
                phw[j] = *(uint32_t*)&bh;
                plw[j] = *(uint32_t*)&bl;
            }
            int woff = (u0 + half * 8) >> 1;
            uint4 vh = make_uint4(phw[0], phw[1], phw[2], phw[3]);
            uint4 vl = make_uint4(plw[0], plw[1], plw[2], plw[3]);
            __stcg((uint4*)&g_hx[d][buf][0][mabs][woff], vh);
            __stcg((uint4*)&g_hx[d][buf][1][mabs][woff], vl);
            *(uint4*)&g_abf[tw][mabs][(d * NA + u0) / 2 + half * 4] = vh;
        }

        __threadfence();
        __syncthreads();
        if (tid == 0)
            asm volatile("red.release.gpu.global.add.u32 [%0], %1;"
                         :: "l"(barp), "r"(1u) : "memory");
    }
}

// ---------------- hoisted attention energies: Ea = a @ W1a^T ----------------
__global__ void ea_kernel(const float* __restrict__ W1)
{
    __shared__ float W1t[512][AH];
    int tid = threadIdx.x;
    for (int i = tid; i < 512 * AH; i += 256) {
        int h = i / 512, k = i - h * 512;
        W1t[k][h] = W1[h * 1024 + k];
    }
    __syncthreads();
    int r = blockIdx.x * 256 + tid;
    const float* arow = &g_a[0][0][0] + (size_t)r * NS;
    float e[AH] = {};
    for (int k = 0; k < 512; k += 4) {
        float4 av = *(const float4*)(arow + k);
        #pragma unroll
        for (int h = 0; h < AH; h++)
            e[h] += av.x * W1t[k][h] + av.y * W1t[k + 1][h]
                  + av.z * W1t[k + 2][h] + av.w * W1t[k + 3][h];
    }
    int tt = r >> 8;
    int m = r & 255;
    float* eo = &g_Ea[m][tt][0];
    #pragma unroll
    for (int h = 0; h < AH; h++) eo[h] = e[h];
}

// ---------------- attention ----------------
__global__ void attention_kernel(const float* __restrict__ W1, const float* __restrict__ b1,
                                 const float* __restrict__ W2, const float* __restrict__ b2,
                                 int pin)
{
    int m = blockIdx.x;
    int tid = threadIdx.x;
    int lane = tid & 31, warp = tid >> 5;
    __shared__ float Ss[NS];
    __shared__ float EsSh[AH];
    __shared__ float alpha[TX];
    __shared__ float red[8];
    __shared__ float sh_mx, sh_sum;

    const float* s_in = &g_sbuf[pin][m][0];
    Ss[tid] = s_in[tid];
    Ss[tid + 256] = s_in[tid + 256];
    __syncthreads();

    for (int h = warp; h < AH; h += 8) {
        float p = 0.f;
        for (int k = lane; k < NS; k += 32)
            p += Ss[k] * W1[h * 1024 + 512 + k];
        #pragma unroll
        for (int o = 16; o; o >>= 1) p += __shfl_xor_sync(0xffffffffu, p, o);
        if (lane == 0) EsSh[h] = p + b1[h];
    }
    __syncthreads();

    float sc = b2[0];
    {
        const float* ea = &g_Ea[m][tid][0];
        #pragma unroll
        for (int h = 0; h < AH; h++)
            sc += W2[h] * tanhf(ea[h] + EsSh[h]);
    }
    sc = fmaxf(sc, 0.f);

    float v = sc;
    #pragma unroll
    for (int o = 16; o; o >>= 1) v = fmaxf(v, __shfl_xor_sync(0xffffffffu, v, o));
    if (lane == 0) red[warp] = v;
    __syncthreads();
    if (tid == 0) {
        float mx = red[0];
        #pragma unroll
        for (int i = 1; i < 8; i++) mx = fmaxf(mx, red[i]);
        sh_mx = mx;
    }
    __syncthreads();
    float ev = expf(sc - sh_mx);
    float sv = ev;
    #pragma unroll
    for (int o = 16; o; o >>= 1) sv += __shfl_xor_sync(0xffffffffu, sv, o);
    if (lane == 0) red[warp] = sv;
    __syncthreads();
    if (tid == 0) {
        float s = 0.f;
        #pragma unroll
        for (int i = 0; i < 8; i++) s += red[i];
        sh_sum = s;
    }
    __syncthreads();
    alpha[tid] = ev / sh_sum;
    __syncthreads();

    const unsigned* ab = &g_abf[0][m][0] + tid;
    float ax = 0.f, ay = 0.f;
    #pragma unroll 8
    for (int t2 = 0; t2 < TX; t2++) {
        unsigned p = ab[(size_t)t2 * MB * (NS / 2)];
        __nv_bfloat162 b2v = *(__nv_bfloat162*)&p;
        float2 vv = __bfloat1622float2(b2v);
        float al = alpha[t2];
        ax += al * vv.x;
        ay += al * vv.y;
    }
    g_ctx[m][2 * tid + 0] = ax;
    g_ctx[m][2 * tid + 1] = ay;
}

// ---------------- decoder LSTM cell (f32x2) ----------------
__global__ void dec_cell_kernel(const float* __restrict__ Wih, const float* __restrict__ Whh,
                                const float* __restrict__ bc, int pin)
{
    int u0 = blockIdx.x * 16;
    int m0 = blockIdx.y * 64;
    int tid = threadIdx.x;
    int ul = tid & 15, mg = tid >> 4;
    int u = u0 + ul;

    __shared__ float As[32][68];
    __shared__ float Ws[32][132];

    unsigned long long acc2[2][4];
    #pragma unroll
    for (int g = 0; g < 4; g++) {
        float b = bc[g * NS + u];
        PACK2(acc2[0][g], b, b);
        acc2[1][g] = acc2[0][g];
    }

    for (int ph = 0; ph < 2; ph++) {
        const float* Arow = ph ? &g_sbuf[pin][0][0] : &g_ctx[0][0];
        const float* W = ph ? Whh : Wih;
        for (int k0 = 0; k0 < NS; k0 += 32) {
            #pragma unroll
            for (int i = 0; i < 2; i++) {
                int lin = tid + 256 * i;
                int mm = lin >> 3, kq = lin & 7;
                float4 f = *(const float4*)&Arow[(size_t)(m0 + mm) * NS + k0 + kq * 4];
                As[kq * 4 + 0][mm] = f.x; As[kq * 4 + 1][mm] = f.y;
                As[kq * 4 + 2][mm] = f.z; As[kq * 4 + 3][mm] = f.w;
            }
            #pragma unroll
            for (int i = 0; i < 2; i++) {
                int lin = tid + 256 * i;
                int r = lin >> 3, kq = lin & 7;
                int uu = r >> 2, g = r & 3;
                float4 f = *(const float4*)&W[(size_t)(g * NS + u0 + uu) * NS + k0 + kq * 4];
                float vv[4] = {f.x, f.y, f.z, f.w};
                #pragma unroll
                for (int j = 0; j < 4; j++)
                    *(float2*)&Ws[kq * 4 + j][r * 2] = make_float2(vv[j], vv[j]);
            }
            __syncthreads();
            #pragma unroll 8
            for (int kk = 0; kk < 32; kk++) {
                ulonglong2 ap = *(const ulonglong2*)&As[kk][mg * 4];
                ulonglong2 wA = *(const ulonglong2*)&Ws[kk][ul * 8];
                ulonglong2 wB = *(const ulonglong2*)&Ws[kk][ul * 8 + 4];
                FMA2(acc2[0][0], ap.x, wA.x); FMA2(acc2[0][1], ap.x, wA.y);
                FMA2(acc2[0][2], ap.x, wB.x); FMA2(acc2[0][3], ap.x, wB.y);
                FMA2(acc2[1][0], ap.y, wA.x); FMA2(acc2[1][1], ap.y, wA.y);
                FMA2(acc2[1][2], ap.y, wB.x); FMA2(acc2[1][3], ap.y, wB.y);
            }
            __syncthreads();
        }
    }

    #pragma unroll
    for (int p = 0; p < 2; p++) {
        float i0, i1, f0, f1, g0, g1, o0, o1;
        UNPACK2(i0, i1, acc2[p][0]);
        UNPACK2(f0, f1, acc2[p][1]);
        UNPACK2(g0, g1, acc2[p][2]);
        UNPACK2(o0, o1, acc2[p][3]);
        {
            int m = m0 + mg * 4 + 2 * p;
            float co = g_cdec[m][u];
            float cn = sigf(f0) * co + sigf(i0) * tanhf(g0);
            g_cdec[m][u] = cn;
            g_sbuf[1 - pin][m][u] = sigf(o0) * tanhf(cn);
        }
        {
            int m = m0 + mg * 4 + 2 * p + 1;
            float co = g_cdec[m][u];
            float cn = sigf(f1) * co + sigf(i1) * tanhf(g1);
            g_cdec[m][u] = cn;
            g_sbuf[1 - pin][m][u] = sigf(o1) * tanhf(cn);
        }
    }
}

// ---------------- output projection (f32x2) ----------------
__global__ void fc_kernel(const float* __restrict__ Wfc, const float* __restrict__ bfc,
                          float* __restrict__ outp, int ps, int ty)
{
    int col0 = blockIdx.x * 64;
    int m0 = blockIdx.y * 64;
    int tid = threadIdx.x;
    int ry = tid >> 4, rx = tid & 15;

    __shared__ float As[16][68];
    __shared__ float Bs[16][132];

    unsigned long long acc2[2][4];
    #pragma unroll
    for (int p = 0; p < 2; p++)
        #pragma unroll
        for (int j = 0; j < 4; j++) acc2[p][j] = 0ull;

    int lr = tid >> 2;
    int lk4 = (tid & 3) * 4;
    const float* S = &g_sbuf[ps][0][0];

    for (int k0 = 0; k0 < NS; k0 += 16) {
        float4 av = *(const float4*)(S + (size_t)(m0 + lr) * NS + k0 + lk4);
        As[lk4 + 0][lr] = av.x; As[lk4 + 1][lr] = av.y;
        As[lk4 + 2][lr] = av.z; As[lk4 + 3][lr] = av.w;
        float4 bv = *(const float4*)(Wfc + (size_t)(col0 + lr) * NS + k0 + lk4);
        float vv[4] = {bv.x, bv.y, bv.z, bv.w};
        #pragma unroll
        for (int j = 0; j < 4; j++)
            *(float2*)&Bs[lk4 + j][lr * 2] = make_float2(vv[j], vv[j]);
        __syncthreads();
        #pragma unroll
        for (int kk = 0; kk < 16; kk++) {
            ulonglong2 ap = *(const ulonglong2*)&As[kk][ry * 4];
            ulonglong2 w0 = *(const ulonglong2*)&Bs[kk][rx * 8];
            ulonglong2 w1 = *(const ulonglong2*)&Bs[kk][rx * 8 + 4];
            FMA2(acc2[0][0], ap.x, w0.x); FMA2(acc2[0][1], ap.x, w0.y);
            FMA2(acc2[0][2], ap.x, w1.x); FMA2(acc2[0][3], ap.x, w1.y);
            FMA2(acc2[1][0], ap.y, w0.x); FMA2(acc2[1][1], ap.y, w0.y);
            FMA2(acc2[1][2], ap.y, w1.x); FMA2(acc2[1][3], ap.y, w1.y);
        }
        __syncthreads();
    }

    int c = col0 + rx * 4;
    float4 bv = *(const float4*)&bfc[c];
    float r0[4], r1[4], r2[4], r3[4];
    UNPACK2(r0[0], r1[0], acc2[0][0]); UNPACK2(r0[1], r1[1], acc2[0][1]);
    UNPACK2(r0[2], r1[2], acc2[0][2]); UNPACK2(r0[3], r1[3], acc2[0][3]);
    UNPACK2(r2[0], r3[0], acc2[1][0]); UNPACK2(r2[1], r3[1], acc2[1][1]);
    UNPACK2(r2[2], r3[2], acc2[1][2]); UNPACK2(r2[3], r3[3], acc2[1][3]);
    int mA = m0 + ry * 4;
    float* o0 = &outp[((size_t)(mA + 0) * TYD + ty) * VOC + c];
    float* o1 = &outp[((size_t)(mA + 1) * TYD + ty) * VOC + c];
    float* o2 = &outp[((size_t)(mA + 2) * TYD + ty) * VOC + c];
    float* o3 = &outp[((size_t)(mA + 3) * TYD + ty) * VOC + c];
    *(float4*)o0 = make_float4(r0[0] + bv.x, r0[1] + bv.y, r0[2] + bv.z, r0[3] + bv.w);
    *(float4*)o1 = make_float4(r1[0] + bv.x, r1[1] + bv.y, r1[2] + bv.z, r1[3] + bv.w);
    *(float4*)o2 = make_float4(r2[0] + bv.x, r2[1] + bv.y, r2[2] + bv.z, r2[3] + bv.w);
    *(float4*)o3 = make_float4(r3[0] + bv.x, r3[1] + bv.y, r3[2] + bv.z, r3[3] + bv.w);
}

// ---------------- launch ----------------
extern "C" void kernel_launch(void* const* d_in, const int* in_sizes, int n_in,
                              void* d_out, int out_size)
{
    const float* X     = (const float*)d_in[0];
    const float* Wih_f = (const float*)d_in[1];
    const float* Whh_f = (const float*)d_in[2];
    const float* b_f   = (const float*)d_in[3];
    const float* Wih_b = (const float*)d_in[4];
    const float* Whh_b = (const float*)d_in[5];
    const float* b_b   = (const float*)d_in[6];
    const float* W1    = (const float*)d_in[7];
    const float* b1    = (const float*)d_in[8];
    const float* W2    = (const float*)d_in[9];
    const float* b2    = (const float*)d_in[10];
    const float* Wc_ih = (const float*)d_in[11];
    const float* Wc_hh = (const float*)d_in[12];
    const float* bc    = (const float*)d_in[13];
    const float* Wfc   = (const float*)d_in[14];
    const float* bfc   = (const float*)d_in[15];
    float* outp = (float*)d_out;

    const int LSTM_SMEM  = (2 * 256 * BLD + 2 * 64 * ALD) * 2 + 64 * CLD * 4;   // 161,792 B
    const int XPROJ_SMEM = (2 * 128 * XBLD + 2 * 64 * XALD) * 2 + 64 * XCLD * 4; // 90,112 B

    static int smem_set = 0;
    if (!smem_set) {
        cudaFuncSetAttribute(lstm_all_kernel,
                             cudaFuncAttributeMaxDynamicSharedMemorySize, LSTM_SMEM);
        cudaFuncSetAttribute(xproj_kernel,
                             cudaFuncAttributeMaxDynamicSharedMemorySize, XPROJ_SMEM);
        smem_set = 1;
    }

    zero_bar_kernel<<<1, 256>>>();
    init_dec_kernel<<<512, 256>>>();
    xproj_kernel<<<dim3(16, 1024, 2), 128, XPROJ_SMEM>>>(X, Wih_f, b_f, Wih_b, b_b);
    lstm_all_kernel<<<dim3(16, 4, 2), 128, LSTM_SMEM>>>(Whh_f, Whh_b);
    ea_kernel<<<256, 256>>>(W1);

    int pin = 0;
    for (int ty = 0; ty < TYD; ty++) {
        attention_kernel<<<MB, 256>>>(W1, b1, W2, b2, pin);
        dec_cell_kernel<<<dim3(32, 4), 256>>>(Wc_ih, Wc_hh, bc, pin);
        fc_kernel<<<dim3(16, 4), 256>>>(Wfc, bfc, outp, 1 - pin, ty);
        pin = 1 - pin;
    }
}

// round 15
// speedup vs baseline: 1.5440x; 1.1118x over previous
#include <cuda_runtime.h>
#include <cuda_bf16.h>
#include <math.h>
#include <stdint.h>
#include <mma.h>

using namespace nvcuda;

#define MB   256
#define TX   256
#define FDIM 128
#define NA   256
#define NS   512
#define VOC  1024
#define AH   10
#define TYD  10

#define BLD 72     // B smem leading dim (bf16)
#define ALD 272    // lstm A smem leading dim (bf16)
#define CLD 72     // C smem leading dim (float)

#define XBLD 72
#define XALD 136
#define XCLD 72

#define DALD 264   // decoder A smem leading dim (bf16): 256 + 8

// ---------------- scratch ----------------
__device__ float    g_gin[2][TX][MB][4 * NA];   // [m][u*4+g]
__device__ float    g_a[TX][MB][NS];
__device__ unsigned g_abf[TX][MB][NS / 2];
__device__ unsigned g_hx[2][2][2][MB][NA / 2];  // [dir][buf][hi/lo][m][k2]
__device__ float    g_Ea[MB][TX][AH];
__device__ unsigned g_cx[2][MB][NS / 2];        // ctx bf16 planes [pl][m][k2]
__device__ unsigned g_sx[2][2][MB][NS / 2];     // s planes [buf][pl][m][k2]
__device__ float    g_sbuf[2][MB][NS];
__device__ float    g_cdec[MB][NS];
__device__ __nv_bfloat16 g_wdx[2][1024][2048];  // dec W planes [pl][k][c=u*4+g]
__device__ __nv_bfloat16 g_wfx[2][512][1024];   // fc  W planes [pl][k][c]
__device__ unsigned g_bar[8][32];

__device__ __forceinline__ float sigf(float x) { return 1.f / (1.f + expf(-x)); }
__device__ __forceinline__ float fsig(float x) { return __fdividef(1.f, 1.f + __expf(-x)); }
__device__ __forceinline__ float ftanh(float x) { return 1.f - __fdividef(2.f, __expf(2.f * x) + 1.f); }

#define FMA2(acc, a, b) asm("fma.rn.f32x2 %0, %1, %2, %0;" : "+l"(acc) : "l"(a), "l"(b))
#define PACK2(d, lo, hi) asm("mov.b64 %0, {%1, %2};" : "=l"(d) : "f"(lo), "f"(hi))
#define UNPACK2(lo, hi, v) asm("mov.b64 {%0, %1}, %2;" : "=f"(lo), "=f"(hi) : "l"(v))

__global__ void zero_bar_kernel()
{
    int i = threadIdx.x;
    if (i < 256) ((unsigned*)g_bar)[i] = 0u;
}

__global__ void init_dec_kernel()
{
    int i = blockIdx.x * 256 + threadIdx.x;
    if (i < MB * NS) {
        (&g_sbuf[0][0][0])[i] = 0.f;
        (&g_cdec[0][0])[i] = 0.f;
        ((unsigned*)&g_sx[0][0][0][0])[i] = 0u;   // both planes of buf 0
    }
}

// ---------------- weight-split prep (once per launch) ----------------
__global__ void wdx_prep(const float* __restrict__ Wc_ih, const float* __restrict__ Wc_hh)
{
    int idx = blockIdx.x * 256 + threadIdx.x;       // 1024*2048
    int k = idx >> 11, c = idx & 2047;
    int u = c >> 2, g = c & 3;
    float w = (k < NS) ? Wc_ih[(size_t)(g * NS + u) * NS + k]
                       : Wc_hh[(size_t)(g * NS + u) * NS + (k - NS)];
    __nv_bfloat16 hi = __float2bfloat16(w);
    __nv_bfloat16 lo = __float2bfloat16(w - __bfloat162float(hi));
    g_wdx[0][k][c] = hi;
    g_wdx[1][k][c] = lo;
}

__global__ void wfx_prep(const float* __restrict__ Wfc)
{
    int idx = blockIdx.x * 256 + threadIdx.x;       // 512*1024
    int k = idx >> 10, c = idx & 1023;
    float w = Wfc[(size_t)c * NS + k];
    __nv_bfloat16 hi = __float2bfloat16(w);
    __nv_bfloat16 lo = __float2bfloat16(w - __bfloat162float(hi));
    g_wfx[0][k][c] = hi;
    g_wfx[1][k][c] = lo;
}

// ---------------- encoder input projection: wmma bf16-split (unchanged, R14-validated) ----------------
__global__ void __launch_bounds__(128) xproj_kernel(const float* __restrict__ X,
                             const float* __restrict__ Wf, const float* __restrict__ bf,
                             const float* __restrict__ Wb, const float* __restrict__ bb)
{
    extern __shared__ char xsm[];
    __nv_bfloat16* Bhi = (__nv_bfloat16*)xsm;
    __nv_bfloat16* Blo = Bhi + 128 * XBLD;
    __nv_bfloat16* Ahi = Blo + 128 * XBLD;
    __nv_bfloat16* Alo = Ahi + 64 * XALD;
    float*         Cs  = (float*)(Alo + 64 * XALD);

    int d = blockIdx.z;
    const float* W    = d ? Wb : Wf;
    const float* bias = d ? bb : bf;
    int col0 = blockIdx.x * 64;
    int row0 = blockIdx.y * 64;
    int t  = row0 >> 8;
    int m0 = row0 & 255;
    int xt = d ? (TX - 1 - t) : t;

    int tid = threadIdx.x;
    int wid = tid >> 5;
    int lr = tid >> 1, kh = tid & 1;

    {
        const float* xrow = X + ((size_t)(m0 + lr) * TX + xt) * FDIM + kh * 64;
        #pragma unroll
        for (int j = 0; j < 16; j++) {
            float4 v = *(const float4*)(xrow + j * 4);
            float vv[4] = {v.x, v.y, v.z, v.w};
            #pragma unroll
            for (int e = 0; e < 4; e++) {
                __nv_bfloat16 hi = __float2bfloat16(vv[e]);
                __nv_bfloat16 lo = __float2bfloat16(vv[e] - __bfloat162float(hi));
                Ahi[lr * XALD + kh * 64 + j * 4 + e] = hi;
                Alo[lr * XALD + kh * 64 + j * 4 + e] = lo;
            }
        }
    }
    {
        int c = col0 + lr;
        const float* wrow = W + (size_t)c * FDIM + kh * 64;
        #pragma unroll
        for (int j = 0; j < 16; j++) {
            float4 v = *(const float4*)(wrow + j * 4);
            float vv[4] = {v.x, v.y, v.z, v.w};
            #pragma unroll
            for (int e = 0; e < 4; e++) {
                int k = kh * 64 + j * 4 + e;
                __nv_bfloat16 hi = __float2bfloat16(vv[e]);
                __nv_bfloat16 lo = __float2bfloat16(vv[e] - __bfloat162float(hi));
                Bhi[k * XBLD + lr] = hi;
                Blo[k * XBLD + lr] = lo;
            }
        }
    }
    __syncthreads();

    wmma::fragment<wmma::accumulator, 16, 16, 16, float> acc[4];
    #pragma unroll
    for (int n = 0; n < 4; n++) wmma::fill_fragment(acc[n], 0.f);
    int wm = wid * 16;
    #pragma unroll 1
    for (int pass = 0; pass < 3; pass++) {
        const __nv_bfloat16* Ap = (pass == 2) ? Alo : Ahi;
        const __nv_bfloat16* Bp = (pass == 1) ? Blo : Bhi;
        #pragma unroll 1
        for (int kf = 0; kf < 8; kf++) {
            wmma::fragment<wmma::matrix_a, 16, 16, 16, __nv_bfloat16, wmma::row_major> af;
            wmma::load_matrix_sync(af, Ap + wm * XALD + kf * 16, XALD);
            #pragma unroll
            for (int n = 0; n < 4; n++) {
                wmma::fragment<wmma::matrix_b, 16, 16, 16, __nv_bfloat16, wmma::row_major> bfr;
                wmma::load_matrix_sync(bfr, Bp + (kf * 16) * XBLD + n * 16, XBLD);
                wmma::mma_sync(acc[n], af, bfr, acc[n]);
            }
        }
    }
    #pragma unroll
    for (int n = 0; n < 4; n++)
        wmma::store_matrix_sync(Cs + wm * XCLD + n * 16, acc[n], XCLD, wmma::mem_row_major);
    __syncthreads();

    {
        int mloc = tid >> 1, half = tid & 1;
        int m = m0 + mloc;
        float* gp = &g_gin[d][t][m][0];
        int g = col0 >> 8;
        #pragma unroll
        for (int j = 0; j < 32; j++) {
            int cg = col0 + half * 32 + j;
            int u = cg & 255;
            gp[u * 4 + g] = Cs[mloc * XCLD + half * 32 + j] + __ldg(&bias[cg]);
        }
    }
}

// ---------------- persistent recurrence (unchanged, R14-validated) ----------------
__global__ void __launch_bounds__(128, 1) lstm_all_kernel(const float* __restrict__ Whf,
                                                          const float* __restrict__ Whb)
{
    extern __shared__ char smc[];
    __nv_bfloat16* Bhi = (__nv_bfloat16*)smc;
    __nv_bfloat16* Blo = Bhi + 256 * BLD;
    __nv_bfloat16* Ahi = Blo + 256 * BLD;
    __nv_bfloat16* Alo = Ahi + 64 * ALD;
    float*         Cs  = (float*)(Alo + 64 * ALD);

    int d = blockIdx.z;
    const float* W = d ? Whb : Whf;
    int u0 = blockIdx.x * 16;
    int m0 = blockIdx.y * 64;
    int tid = threadIdx.x;
    int wid = tid >> 5;
    unsigned* barp = &g_bar[d * 4 + blockIdx.y][0];

    for (int idx = tid; idx < 256 * 64; idx += 128) {
        int k = idx >> 6, c = idx & 63;
        int ul = c >> 2, g = c & 3;
        float w = W[(size_t)(g * NA + u0 + ul) * NA + k];
        __nv_bfloat16 hi = __float2bfloat16(w);
        __nv_bfloat16 lo = __float2bfloat16(w - __bfloat162float(hi));
        Bhi[k * BLD + c] = hi;
        Blo[k * BLD + c] = lo;
    }

    int mloc = tid >> 1, half = tid & 1;
    int mabs = m0 + mloc;
    float cst[8];
    #pragma unroll
    for (int i = 0; i < 8; i++) cst[i] = 0.f;

    for (int t = 0; t < TX; t++) {
        if (t > 0) {
            if (tid == 0) {
                unsigned tgt = 16u * (unsigned)t;
                unsigned v;
                do {
                    asm volatile("ld.acquire.gpu.global.u32 %0, [%1];"
                                 : "=r"(v) : "l"(barp) : "memory");
                } while (v < tgt);
            }
            __syncthreads();

            int buf = (t - 1) & 1;
            uint4* ah4 = (uint4*)Ahi;
            uint4* al4 = (uint4*)Alo;
            const uint4* ph = (const uint4*)&g_hx[d][buf][0][m0][0];
            const uint4* pl = (const uint4*)&g_hx[d][buf][1][m0][0];
            for (int idx = tid; idx < 64 * 32; idx += 128) {
                int m = idx >> 5, w4 = idx & 31;
                ah4[m * (ALD / 8) + w4] = __ldcg(&ph[idx]);
                al4[m * (ALD / 8) + w4] = __ldcg(&pl[idx]);
            }
        } else {
            uint4 z4 = make_uint4(0u, 0u, 0u, 0u);
            for (int idx = tid; idx < 64 * (ALD / 8); idx += 128) {
                ((uint4*)Ahi)[idx] = z4;
                ((uint4*)Alo)[idx] = z4;
            }
        }
        __syncthreads();

        wmma::fragment<wmma::accumulator, 16, 16, 16, float> acc[4];
        #pragma unroll
        for (int n = 0; n < 4; n++) wmma::fill_fragment(acc[n], 0.f);
        int wm = wid * 16;
        #pragma unroll 1
        for (int pass = 0; pass < 3; pass++) {
            const __nv_bfloat16* Ap = (pass == 2) ? Alo : Ahi;
            const __nv_bfloat16* Bp = (pass == 1) ? Blo : Bhi;
            #pragma unroll 1
            for (int k = 0; k < 16; k++) {
                wmma::fragment<wmma::matrix_a, 16, 16, 16, __nv_bfloat16, wmma::row_major> af;
                wmma::load_matrix_sync(af, Ap + wm * ALD + k * 16, ALD);
                #pragma unroll
                for (int n = 0; n < 4; n++) {
                    wmma::fragment<wmma::matrix_b, 16, 16, 16, __nv_bfloat16, wmma::row_major> bfr;
                    wmma::load_matrix_sync(bfr, Bp + (k * 16) * BLD + n * 16, BLD);
                    wmma::mma_sync(acc[n], af, bfr, acc[n]);
                }
            }
        }
        #pragma unroll
        for (int n = 0; n < 4; n++)
            wmma::store_matrix_sync(Cs + wm * CLD + n * 16, acc[n], CLD, wmma::mem_row_major);
        __syncthreads();

        int tw = d ? (TX - 1 - t) : t;
        int buf = t & 1;
        float gc[32];
        {
            const float4* gp = (const float4*)&g_gin[d][t][mabs][(u0 + half * 8) * 4];
            #pragma unroll
            for (int q = 0; q < 8; q++) *(float4*)&gc[q * 4] = gp[q];
        }
        float h8[8];
        #pragma unroll
        for (int j = 0; j < 8; j++) {
            int col = half * 32 + j * 4;
            float iv = Cs[mloc * CLD + col + 0] + gc[4 * j + 0];
            float fv = Cs[mloc * CLD + col + 1] + gc[4 * j + 1];
            float gv = Cs[mloc * CLD + col + 2] + gc[4 * j + 2];
            float ov = Cs[mloc * CLD + col + 3] + gc[4 * j + 3];
            float cn = fsig(fv) * cst[j] + fsig(iv) * ftanh(gv);
            cst[j] = cn;
            h8[j] = fsig(ov) * ftanh(cn);
        }
        {
            float* ga = &g_a[tw][mabs][d * NA + u0 + half * 8];
            *(float4*)&ga[0] = make_float4(h8[0], h8[1], h8[2], h8[3]);
            *(float4*)&ga[4] = make_float4(h8[4], h8[5], h8[6], h8[7]);
        }
        {
            uint32_t phw[4], plw[4];
            #pragma unroll
            for (int j = 0; j < 4; j++) {
                float f0 = h8[2 * j], f1 = h8[2 * j + 1];
                __nv_bfloat162 bh = __float22bfloat162_rn(make_float2(f0, f1));
                float r0 = f0 - __bfloat162float(__low2bfloat16(bh));
                float r1 = f1 - __bfloat162float(__high2bfloat16(bh));
                __nv_bfloat162 bl = __float22bfloat162_rn(make_float2(r0, r1));
                phw[j] = *(uint32_t*)&bh;
                plw[j] = *(uint32_t*)&bl;
            }
            int woff = (u0 + half * 8) >> 1;
            uint4 vh = make_uint4(phw[0], phw[1], phw[2], phw[3]);
            uint4 vl = make_uint4(plw[0], plw[1], plw[2], plw[3]);
            __stcg((uint4*)&g_hx[d][buf][0][mabs][woff], vh);
            __stcg((uint4*)&g_hx[d][buf][1][mabs][woff], vl);
            *(uint4*)&g_abf[tw][mabs][(d * NA + u0) / 2 + half * 4] = vh;
        }

        __threadfence();
        __syncthreads();
        if (tid == 0)
            asm volatile("red.release.gpu.global.add.u32 [%0], %1;"
                         :: "l"(barp), "r"(1u) : "memory");
    }
}

// ---------------- hoisted attention energies ----------------
__global__ void ea_kernel(const float* __restrict__ W1)
{
    __shared__ float W1t[512][AH];
    int tid = threadIdx.x;
    for (int i = tid; i < 512 * AH; i += 256) {
        int h = i / 512, k = i - h * 512;
        W1t[k][h] = W1[h * 1024 + k];
    }
    __syncthreads();
    int r = blockIdx.x * 256 + tid;
    const float* arow = &g_a[0][0][0] + (size_t)r * NS;
    float e[AH] = {};
    for (int k = 0; k < 512; k += 4) {
        float4 av = *(const float4*)(arow + k);
        #pragma unroll
        for (int h = 0; h < AH; h++)
            e[h] += av.x * W1t[k][h] + av.y * W1t[k + 1][h]
                  + av.z * W1t[k + 2][h] + av.w * W1t[k + 3][h];
    }
    int tt = r >> 8;
    int m = r & 255;
    float* eo = &g_Ea[m][tt][0];
    #pragma unroll
    for (int h = 0; h < AH; h++) eo[h] = e[h];
}

// ---------------- attention: now emits ctx as bf16 hi/lo planes ----------------
__global__ void attention_kernel(const float* __restrict__ W1, const float* __restrict__ b1,
                                 const float* __restrict__ W2, const float* __restrict__ b2,
                                 int pin)
{
    int m = blockIdx.x;
    int tid = threadIdx.x;
    int lane = tid & 31, warp = tid >> 5;
    __shared__ float Ss[NS];
    __shared__ float EsSh[AH];
    __shared__ float alpha[TX];
    __shared__ float red[8];
    __shared__ float sh_mx, sh_sum;

    const float* s_in = &g_sbuf[pin][m][0];
    Ss[tid] = s_in[tid];
    Ss[tid + 256] = s_in[tid + 256];
    __syncthreads();

    for (int h = warp; h < AH; h += 8) {
        float p = 0.f;
        for (int k = lane; k < NS; k += 32)
            p += Ss[k] * W1[h * 1024 + 512 + k];
        #pragma unroll
        for (int o = 16; o; o >>= 1) p += __shfl_xor_sync(0xffffffffu, p, o);
        if (lane == 0) EsSh[h] = p + b1[h];
    }
    __syncthreads();

    float sc = b2[0];
    {
        const float* ea = &g_Ea[m][tid][0];
        #pragma unroll
        for (int h = 0; h < AH; h++)
            sc += W2[h] * tanhf(ea[h] + EsSh[h]);
    }
    sc = fmaxf(sc, 0.f);

    float v = sc;
    #pragma unroll
    for (int o = 16; o; o >>= 1) v = fmaxf(v, __shfl_xor_sync(0xffffffffu, v, o));
    if (lane == 0) red[warp] = v;
    __syncthreads();
    if (tid == 0) {
        float mx = red[0];
        #pragma unroll
        for (int i = 1; i < 8; i++) mx = fmaxf(mx, red[i]);
        sh_mx = mx;
    }
    __syncthreads();
    float ev = expf(sc - sh_mx);
    float sv = ev;
    #pragma unroll
    for (int o = 16; o; o >>= 1) sv += __shfl_xor_sync(0xffffffffu, sv, o);
    if (lane == 0) red[warp] = sv;
    __syncthreads();
    if (tid == 0) {
        float s = 0.f;
        #pragma unroll
        for (int i = 0; i < 8; i++) s += red[i];
        sh_sum = s;
    }
    __syncthreads();
    alpha[tid] = ev / sh_sum;
    __syncthreads();

    const unsigned* ab = &g_abf[0][m][0] + tid;
    float ax = 0.f, ay = 0.f;
    #pragma unroll 8
    for (int t2 = 0; t2 < TX; t2++) {
        unsigned p = ab[(size_t)t2 * MB * (NS / 2)];
        __nv_bfloat162 b2v = *(__nv_bfloat162*)&p;
        float2 vv = __bfloat1622float2(b2v);
        float al = alpha[t2];
        ax += al * vv.x;
        ay += al * vv.y;
    }
    // split ctx into bf16 hi/lo planes
    __nv_bfloat162 bh = __float22bfloat162_rn(make_float2(ax, ay));
    float r0 = ax - __bfloat162float(__low2bfloat16(bh));
    float r1 = ay - __bfloat162float(__high2bfloat16(bh));
    __nv_bfloat162 bl = __float22bfloat162_rn(make_float2(r0, r1));
    g_cx[0][m][tid] = *(unsigned*)&bh;
    g_cx[1][m][tid] = *(unsigned*)&bl;
}

// ---------------- decoder LSTM cell: wmma bf16-split, K=1024 in 4 chunks ----------------
// grid (32 c-tiles, 4 m-tiles), 128 threads. cols c = u*4+g (2048 total).
__global__ void __launch_bounds__(128) dec_cell_kernel(const float* __restrict__ bc, int pin)
{
    extern __shared__ char dsm[];
    __nv_bfloat16* Bhi = (__nv_bfloat16*)dsm;           // [256][BLD]
    __nv_bfloat16* Blo = Bhi + 256 * BLD;
    __nv_bfloat16* Ahi = Blo + 256 * BLD;               // [64][DALD]
    __nv_bfloat16* Alo = Ahi + 64 * DALD;
    float*         Cs  = (float*)(Alo + 64 * DALD);     // [64][CLD]

    int u0c = blockIdx.x * 64;       // col base
    int m0  = blockIdx.y * 64;
    int tid = threadIdx.x;
    int wid = tid >> 5;

    wmma::fragment<wmma::accumulator, 16, 16, 16, float> acc[4];
    #pragma unroll
    for (int n = 0; n < 4; n++) wmma::fill_fragment(acc[n], 0.f);
    int wm = wid * 16;

    #pragma unroll 1
    for (int kc = 0; kc < 4; kc++) {
        // A chunk: k in [kc*256, +256): kc<2 -> ctx planes, else s planes
        {
            const uint4* srcH;
            const uint4* srcL;
            int koff = kc & 1;                        // chunk-within-source
            if (kc < 2) {
                srcH = (const uint4*)&g_cx[0][m0][0];
                srcL = (const uint4*)&g_cx[1][m0][0];
            } else {
                srcH = (const uint4*)&g_sx[pin][0][m0][0];
                srcL = (const uint4*)&g_sx[pin][1][m0][0];
            }
            for (int idx = tid; idx < 64 * 32; idx += 128) {
                int m = idx >> 5, w4 = idx & 31;
                int src_i = m * 64 + koff * 32 + w4;  // row = 64 uint4
                ((uint4*)Ahi)[m * (DALD / 8) + w4] = __ldcg(&srcH[src_i]);
                ((uint4*)Alo)[m * (DALD / 8) + w4] = __ldcg(&srcL[src_i]);
            }
        }
        // B chunk: g_wdx[pl][kc*256 + k][u0c .. +63]
        for (int idx = tid; idx < 256 * 8; idx += 128) {
            int k = idx >> 3, q = idx & 7;
            ((uint4*)Bhi)[k * (BLD / 8) + q] =
                __ldcg((const uint4*)&g_wdx[0][kc * 256 + k][u0c] + q);
            ((uint4*)Blo)[k * (BLD / 8) + q] =
                __ldcg((const uint4*)&g_wdx[1][kc * 256 + k][u0c] + q);
        }
        __syncthreads();

        #pragma unroll 1
        for (int pass = 0; pass < 3; pass++) {
            const __nv_bfloat16* Ap = (pass == 2) ? Alo : Ahi;
            const __nv_bfloat16* Bp = (pass == 1) ? Blo : Bhi;
            #pragma unroll 1
            for (int k = 0; k < 16; k++) {
                wmma::fragment<wmma::matrix_a, 16, 16, 16, __nv_bfloat16, wmma::row_major> af;
                wmma::load_matrix_sync(af, Ap + wm * DALD + k * 16, DALD);
                #pragma unroll
                for (int n = 0; n < 4; n++) {
                    wmma::fragment<wmma::matrix_b, 16, 16, 16, __nv_bfloat16, wmma::row_major> bfr;
                    wmma::load_matrix_sync(bfr, Bp + (k * 16) * BLD + n * 16, BLD);
                    wmma::mma_sync(acc[n], af, bfr, acc[n]);
                }
            }
        }
        __syncthreads();
    }
    #pragma unroll
    for (int n = 0; n < 4; n++)
        wmma::store_matrix_sync(Cs + wm * CLD + n * 16, acc[n], CLD, wmma::mem_row_major);
    __syncthreads();

    // ---- epilogue: thread (mloc, half); 8 units each ----
    int mloc = tid >> 1, half = tid & 1;
    int m = m0 + mloc;
    int ub = u0c / 4 + half * 8;                 // global unit base
    float s8[8];
    #pragma unroll
    for (int j = 0; j < 8; j++) {
        int u = ub + j;
        int col = half * 32 + j * 4;
        float iv = Cs[mloc * CLD + col + 0] + __ldg(&bc[0 * NS + u]);
        float fv = Cs[mloc * CLD + col + 1] + __ldg(&bc[1 * NS + u]);
        float gv = Cs[mloc * CLD + col + 2] + __ldg(&bc[2 * NS + u]);
        float ov = Cs[mloc * CLD + col + 3] + __ldg(&bc[3 * NS + u]);
        float co = g_cdec[m][u];
        float cn = sigf(fv) * co + sigf(iv) * tanhf(gv);
        g_cdec[m][u] = cn;
        s8[j] = sigf(ov) * tanhf(cn);
    }
    {
        float* sb = &g_sbuf[1 - pin][m][ub];
        *(float4*)&sb[0] = make_float4(s8[0], s8[1], s8[2], s8[3]);
        *(float4*)&sb[4] = make_float4(s8[4], s8[5], s8[6], s8[7]);
        uint32_t phw[4], plw[4];
        #pragma unroll
        for (int j = 0; j < 4; j++) {
            float f0 = s8[2 * j], f1 = s8[2 * j + 1];
            __nv_bfloat162 bh = __float22bfloat162_rn(make_float2(f0, f1));
            float r0 = f0 - __bfloat162float(__low2bfloat16(bh));
            float r1 = f1 - __bfloat162float(__high2bfloat16(bh));
            __nv_bfloat162 bl = __float22bfloat162_rn(make_float2(r0, r1));
            phw[j] = *(uint32_t*)&bh;
            plw[j] = *(uint32_t*)&bl;
        }
        *(uint4*)&g_sx[1 - pin][0][m][ub >> 1] = make_uint4(phw[0], phw[1], phw[2], phw[3]);
        *(uint4*)&g_sx[1 - pin][1][m][ub >> 1] = make_uint4(plw[0], plw[1], plw[2], plw[3]);
    }
}

// ---------------- output projection: wmma bf16-split, K=512 in 2 chunks ----------------
__global__ void __launch_bounds__(128) fc_kernel(const float* __restrict__ bfc,
                                                 float* __restrict__ outp, int ps, int ty)
{
    extern __shared__ char fsm[];
    __nv_bfloat16* Bhi = (__nv_bfloat16*)fsm;           // [256][BLD]
    __nv_bfloat16* Blo = Bhi + 256 * BLD;
    __nv_bfloat16* Ahi = Blo + 256 * BLD;               // [64][DALD]
    __nv_bfloat16* Alo = Ahi + 64 * DALD;
    float*         Cs  = (float*)(Alo + 64 * DALD);

    int col0 = blockIdx.x * 64;
    int m0   = blockIdx.y * 64;
    int tid = threadIdx.x;
    int wid = tid >> 5;

    wmma::fragment<wmma::accumulator, 16, 16, 16, float> acc[4];
    #pragma unroll
    for (int n = 0; n < 4; n++) wmma::fill_fragment(acc[n], 0.f);
    int wm = wid * 16;

    #pragma unroll 1
    for (int kc = 0; kc < 2; kc++) {
        {
            const uint4* srcH = (const uint4*)&g_sx[ps][0][m0][0];
            const uint4* srcL = (const uint4*)&g_sx[ps][1][m0][0];
            for (int idx = tid; idx < 64 * 32; idx += 128) {
                int m = idx >> 5, w4 = idx & 31;
                int src_i = m * 64 + kc * 32 + w4;
                ((uint4*)Ahi)[m * (DALD / 8) + w4] = __ldcg(&srcH[src_i]);
                ((uint4*)Alo)[m * (DALD / 8) + w4] = __ldcg(&srcL[src_i]);
            }
        }
        for (int idx = tid; idx < 256 * 8; idx += 128) {
            int k = idx >> 3, q = idx & 7;
            ((uint4*)Bhi)[k * (BLD / 8) + q] =
                __ldcg((const uint4*)&g_wfx[0][kc * 256 + k][col0] + q);
            ((uint4*)Blo)[k * (BLD / 8) + q] =
                __ldcg((const uint4*)&g_wfx[1][kc * 256 + k][col0] + q);
        }
        __syncthreads();

        #pragma unroll 1
        for (int pass = 0; pass < 3; pass++) {
            const __nv_bfloat16* Ap = (pass == 2) ? Alo : Ahi;
            const __nv_bfloat16* Bp = (pass == 1) ? Blo : Bhi;
            #pragma unroll 1
            for (int k = 0; k < 16; k++) {
                wmma::fragment<wmma::matrix_a, 16, 16, 16, __nv_bfloat16, wmma::row_major> af;
                wmma::load_matrix_sync(af, Ap + wm * DALD + k * 16, DALD);
                #pragma unroll
                for (int n = 0; n < 4; n++) {
                    wmma::fragment<wmma::matrix_b, 16, 16, 16, __nv_bfloat16, wmma::row_major> bfr;
                    wmma::load_matrix_sync(bfr, Bp + (k * 16) * BLD + n * 16, BLD);
                    wmma::mma_sync(acc[n], af, bfr, acc[n]);
                }
            }
        }
        __syncthreads();
    }
    #pragma unroll
    for (int n = 0; n < 4; n++)
        wmma::store_matrix_sync(Cs + wm * CLD + n * 16, acc[n], CLD, wmma::mem_row_major);
    __syncthreads();

    int mloc = tid >> 1, half = tid & 1;
    int m = m0 + mloc;
    float* op = &outp[((size_t)m * TYD + ty) * VOC + col0 + half * 32];
    #pragma unroll
    for (int q = 0; q < 8; q++) {
        int j = q * 4;
        float4 bv = *(const float4*)&bfc[col0 + half * 32 + j];
        *(float4*)&op[j] = make_float4(Cs[mloc * CLD + half * 32 + j + 0] + bv.x,
                                       Cs[mloc * CLD + half * 32 + j + 1] + bv.y,
                                       Cs[mloc * CLD + half * 32 + j + 2] + bv.z,
                                       Cs[mloc * CLD + half * 32 + j + 3] + bv.w);
    }
}

// ---------------- launch ----------------
extern "C" void kernel_launch(void* const* d_in, const int* in_sizes, int n_in,
                              void* d_out, int out_size)
{
    const float* X     = (const float*)d_in[0];
    const float* Wih_f = (const float*)d_in[1];
    const float* Whh_f = (const float*)d_in[2];
    const float* b_f   = (const float*)d_in[3];
    const float* Wih_b = (const float*)d_in[4];
    const float* Whh_b = (const float*)d_in[5];
    const float* b_b   = (const float*)d_in[6];
    const float* W1    = (const float*)d_in[7];
    const float* b1    = (const float*)d_in[8];
    const float* W2    = (const float*)d_in[9];
    const float* b2    = (const float*)d_in[10];
    const float* Wc_ih = (const float*)d_in[11];
    const float* Wc_hh = (const float*)d_in[12];
    const float* bc    = (const float*)d_in[13];
    const float* Wfc   = (const float*)d_in[14];
    const float* bfc   = (const float*)d_in[15];
    float* outp = (float*)d_out;

    const int LSTM_SMEM  = (2 * 256 * BLD + 2 * 64 * ALD) * 2 + 64 * CLD * 4;
    const int XPROJ_SMEM = (2 * 128 * XBLD + 2 * 64 * XALD) * 2 + 64 * XCLD * 4;
    const int DEC_SMEM   = (2 * 256 * BLD + 2 * 64 * DALD) * 2 + 64 * CLD * 4;

    static int smem_set = 0;
    if (!smem_set) {
        cudaFuncSetAttribute(lstm_all_kernel,
                             cudaFuncAttributeMaxDynamicSharedMemorySize, LSTM_SMEM);
        cudaFuncSetAttribute(xproj_kernel,
                             cudaFuncAttributeMaxDynamicSharedMemorySize, XPROJ_SMEM);
        cudaFuncSetAttribute(dec_cell_kernel,
                             cudaFuncAttributeMaxDynamicSharedMemorySize, DEC_SMEM);
        cudaFuncSetAttribute(fc_kernel,
                             cudaFuncAttributeMaxDynamicSharedMemorySize, DEC_SMEM);
        smem_set = 1;
    }

    zero_bar_kernel<<<1, 256>>>();
    init_dec_kernel<<<512, 256>>>();
    wdx_prep<<<8192, 256>>>(Wc_ih, Wc_hh);
    wfx_prep<<<2048, 256>>>(Wfc);
    xproj_kernel<<<dim3(16, 1024, 2), 128, XPROJ_SMEM>>>(X, Wih_f, b_f, Wih_b, b_b);
    lstm_all_kernel<<<dim3(16, 4, 2), 128, LSTM_SMEM>>>(Whh_f, Whh_b);
    ea_kernel<<<256, 256>>>(W1);

    int pin = 0;
    for (int ty = 0; ty < TYD; ty++) {
        attention_kernel<<<MB, 256>>>(W1, b1, W2, b2, pin);
        dec_cell_kernel<<<dim3(32, 4), 128, DEC_SMEM>>>(bc, pin);
        fc_kernel<<<dim3(16, 4), 128, DEC_SMEM>>>(bfc, outp, 1 - pin, ty);
        pin = 1 - pin;
    }
}